// round 9
// baseline (speedup 1.0000x reference)
#include <cuda_runtime.h>
#include <cuda_bf16.h>
#include <cstdint>

// Problem constants
#define C_DIM 1024
#define B_DIM 4
#define T_DIM 2048
#define H_DIM 16
#define DH_DIM 64
#define M_DIM (B_DIM * T_DIM)   // 8192

// ===========================================================================
// Scratch (__device__ globals; no cudaMalloc allowed)
// ===========================================================================
__device__ __nv_bfloat16  g_Xh [M_DIM * C_DIM];   // x hi/lo split
__device__ __nv_bfloat16  g_Xl [M_DIM * C_DIM];
__device__ __nv_bfloat16  g_Qh [M_DIM * C_DIM], g_Ql [M_DIM * C_DIM];
__device__ __nv_bfloat16  g_Kh [M_DIM * C_DIM], g_Kl [M_DIM * C_DIM];
__device__ __nv_bfloat16  g_Vh [M_DIM * C_DIM], g_Vl [M_DIM * C_DIM];
__device__ __nv_bfloat16  g_Ah [M_DIM * C_DIM], g_Al [M_DIM * C_DIM];
// weights as [N][K] bf16 hi/lo (B operand of mma .col = K-major [N,K] rows)
__device__ __nv_bfloat16  g_Wqh[C_DIM * C_DIM], g_Wql[C_DIM * C_DIM];
__device__ __nv_bfloat16  g_Wkh[C_DIM * C_DIM], g_Wkl[C_DIM * C_DIM];
__device__ __nv_bfloat16  g_Wvh[C_DIM * C_DIM], g_Wvl[C_DIM * C_DIM];
__device__ __nv_bfloat16  g_Woh[C_DIM * C_DIM], g_Wol[C_DIM * C_DIM];

__device__ __forceinline__ void split_bf16(float v, __nv_bfloat16& h, __nv_bfloat16& l) {
    __nv_bfloat16 hi = __float2bfloat16(v);
    h = hi;
    l = __float2bfloat16(v - __bfloat162float(hi));
}
__device__ __forceinline__ uint32_t pack2(__nv_bfloat16 lo, __nv_bfloat16 hi) {
    __nv_bfloat162 t(lo, hi);
    return reinterpret_cast<uint32_t&>(t);
}

// ---------------------------------------------------------------------------
// Weight prep: [H,C,DH] -> [n=h*64+d][c] bf16 hi/lo; Wo [j][c] is already [N][K].
// ---------------------------------------------------------------------------
__global__ void prep_weights(const float* __restrict__ Wq,
                             const float* __restrict__ Wk,
                             const float* __restrict__ Wv,
                             const float* __restrict__ Wo)
{
    int i = blockIdx.x * blockDim.x + threadIdx.x;   // i = n*1024 + c
    int n = i >> 10;
    int c = i & 1023;
    int h = n >> 6;
    int d = n & 63;
    int src = (h << 16) + (c << 6) + d;              // h*C*DH + c*DH + d
    split_bf16(Wq[src], g_Wqh[i], g_Wql[i]);
    split_bf16(Wk[src], g_Wkh[i], g_Wkl[i]);
    split_bf16(Wv[src], g_Wvh[i], g_Wvl[i]);
    split_bf16(Wo[i],   g_Woh[i], g_Wol[i]);
}

__global__ void split_x(const float* __restrict__ x)
{
    int i = blockIdx.x * blockDim.x + threadIdx.x;
    split_bf16(x[i], g_Xh[i], g_Xl[i]);
}

// ===========================================================================
// PTX wrappers (all plain sm_80+ — assemble under compute_103)
// ===========================================================================
__device__ __forceinline__ uint32_t smem_u32(const void* p) {
    uint32_t a;
    asm("{ .reg .u64 t; cvta.to.shared.u64 t, %1; cvt.u32.u64 %0, t; }"
        : "=r"(a) : "l"(p));
    return a;
}
__device__ __forceinline__ void ldsm4(uint32_t* r, uint32_t addr) {
    asm volatile("ldmatrix.sync.aligned.m8n8.x4.shared.b16 {%0,%1,%2,%3}, [%4];"
                 : "=r"(r[0]), "=r"(r[1]), "=r"(r[2]), "=r"(r[3]) : "r"(addr));
}
__device__ __forceinline__ void ldsm4t(uint32_t* r, uint32_t addr) {
    asm volatile("ldmatrix.sync.aligned.m8n8.x4.trans.shared.b16 {%0,%1,%2,%3}, [%4];"
                 : "=r"(r[0]), "=r"(r[1]), "=r"(r[2]), "=r"(r[3]) : "r"(addr));
}
__device__ __forceinline__ void mma16816(float* c, const uint32_t* a, const uint32_t* b) {
    asm volatile("mma.sync.aligned.m16n8k16.row.col.f32.bf16.bf16.f32 "
                 "{%0,%1,%2,%3}, {%4,%5,%6,%7}, {%8,%9}, {%0,%1,%2,%3};"
                 : "+f"(c[0]), "+f"(c[1]), "+f"(c[2]), "+f"(c[3])
                 : "r"(a[0]), "r"(a[1]), "r"(a[2]), "r"(a[3]),
                   "r"(b[0]), "r"(b[1]));
}
#define CP_ASYNC16(saddr, gptr) \
    asm volatile("cp.async.cg.shared.global [%0], [%1], 16;" \
                 :: "r"(saddr), "l"(gptr) : "memory")
#define CP_COMMIT()  asm volatile("cp.async.commit_group;" ::: "memory")
#define CP_WAIT0()   asm volatile("cp.async.wait_group 0;" ::: "memory")
#define CP_WAIT1()   asm volatile("cp.async.wait_group 1;" ::: "memory")

// ===========================================================================
// bf16 hi/lo GEMM, 2-stage pipelined: C = A[M,K]*B[N,K]^T, 3-term compensation.
// Block 128x128, 8 warps (4m x 2n), warp tile 32x64. K-chunk 16, pitch 48B
// (ldmatrix phase start banks 12r mod 32 = perfect 4-bank partition).
// Stage = 4 tiles x 6144B = 24576B; 2 stages = 49152B static (48KB limit).
// Output: fp32 (+bias) if outh==null, else bf16 hi/lo split pair.
// ===========================================================================
#define GP      48
#define GT      (128 * GP)             // 6144 bytes per tile
#define GSTG    (4 * GT)               // 24576 per stage

__global__ __launch_bounds__(256, 2)
void gemm_mma(const __nv_bfloat16* __restrict__ Ahp, const __nv_bfloat16* __restrict__ Alp,
              const __nv_bfloat16* __restrict__ Bhp, const __nv_bfloat16* __restrict__ Blp,
              float* __restrict__ Cmat, const float* __restrict__ bias,
              __nv_bfloat16* __restrict__ outh, __nv_bfloat16* __restrict__ outl,
              int Nglob, int Kglob)
{
    __shared__ char sm[2 * GSTG];      // 49152 B static
    const uint32_t sb = smem_u32(sm);

    const int tid  = threadIdx.x;
    const int lane = tid & 31;
    const int wid  = tid >> 5;
    const int wm   = wid & 3;
    const int wn   = wid >> 2;

    const int row0 = blockIdx.y * 128;
    const int col0 = blockIdx.x * 128;

    // gmem load mapping: thread covers one 16B block per tile per chunk
    const int rg = tid >> 1;                  // row 0..127
    const int cg = tid & 1;                   // 16B col block 0..1
    const __nv_bfloat16* pAh0 = Ahp + (size_t)(row0 + rg) * Kglob + cg * 8;
    const __nv_bfloat16* pAl0 = Alp + (size_t)(row0 + rg) * Kglob + cg * 8;
    const __nv_bfloat16* pBh0 = Bhp + (size_t)(col0 + rg) * Kglob + cg * 8;
    const __nv_bfloat16* pBl0 = Blp + (size_t)(col0 + rg) * Kglob + cg * 8;
    const uint32_t s0 = (uint32_t)(rg * GP + cg * 16);

    const int a_row = (lane & 7) + ((lane >> 3) & 1) * 8;
    const int a_kb  = (lane >> 4);
    const int b_row = (lane & 7) + ((lane >> 4) & 1) * 8;
    const int b_kb  = (lane >> 3) & 1;

    float acc[2][8][4];
#pragma unroll
    for (int mi = 0; mi < 2; mi++)
#pragma unroll
        for (int nf = 0; nf < 8; nf++)
#pragma unroll
            for (int e = 0; e < 4; e++) acc[mi][nf][e] = 0.f;

    const int NCH = Kglob >> 4;        // chunks of 16
    // prologue: load chunk 0 into stage 0
    {
        uint32_t base = sb + s0;
        CP_ASYNC16(base + 0 * GT, pAh0);
        CP_ASYNC16(base + 1 * GT, pAl0);
        CP_ASYNC16(base + 2 * GT, pBh0);
        CP_ASYNC16(base + 3 * GT, pBl0);
        CP_COMMIT();
    }

    for (int ch = 0; ch < NCH; ch++) {
        const int buf = ch & 1;
        if (ch + 1 < NCH) {            // issue next chunk into other stage
            const int k1 = (ch + 1) << 4;
            uint32_t base = sb + (buf ^ 1) * GSTG + s0;
            CP_ASYNC16(base + 0 * GT, pAh0 + k1);
            CP_ASYNC16(base + 1 * GT, pAl0 + k1);
            CP_ASYNC16(base + 2 * GT, pBh0 + k1);
            CP_ASYNC16(base + 3 * GT, pBl0 + k1);
            CP_COMMIT();
            CP_WAIT1();                // chunk ch resident, ch+1 in flight
        } else {
            CP_WAIT0();
        }
        __syncthreads();

        const uint32_t base = sb + buf * GSTG;
        uint32_t ah[2][4], al[2][4], bh[4][4], bl[4][4];
#pragma unroll
        for (int mi = 0; mi < 2; mi++) {
            uint32_t ar = base + (uint32_t)((wm * 32 + mi * 16 + a_row) * GP + a_kb * 16);
            ldsm4(ah[mi], ar + 0 * GT);
            ldsm4(al[mi], ar + 1 * GT);
        }
#pragma unroll
        for (int p = 0; p < 4; p++) {
            uint32_t br = base + (uint32_t)((wn * 64 + p * 16 + b_row) * GP + b_kb * 16);
            ldsm4(bh[p], br + 2 * GT);
            ldsm4(bl[p], br + 3 * GT);
        }
#pragma unroll
        for (int mi = 0; mi < 2; mi++)
#pragma unroll
            for (int p = 0; p < 4; p++) {
                mma16816(acc[mi][2 * p + 0], ah[mi], &bh[p][0]);
                mma16816(acc[mi][2 * p + 0], ah[mi], &bl[p][0]);
                mma16816(acc[mi][2 * p + 0], al[mi], &bh[p][0]);
                mma16816(acc[mi][2 * p + 1], ah[mi], &bh[p][2]);
                mma16816(acc[mi][2 * p + 1], ah[mi], &bl[p][2]);
                mma16816(acc[mi][2 * p + 1], al[mi], &bh[p][2]);
            }
        __syncthreads();               // buffer free before iter ch+1 overwrites
    }

    const int tq = lane >> 2;
    const int tr = lane & 3;
#pragma unroll
    for (int mi = 0; mi < 2; mi++) {
        int rbase = row0 + wm * 32 + mi * 16 + tq;
#pragma unroll
        for (int nf = 0; nf < 8; nf++) {
            int col = col0 + wn * 64 + nf * 8 + tr * 2;
            if (outh) {
                __nv_bfloat16 h0, l0, h1, l1;
                split_bf16(acc[mi][nf][0], h0, l0);
                split_bf16(acc[mi][nf][1], h1, l1);
                *(uint32_t*)&outh[(size_t)rbase * Nglob + col] = pack2(h0, h1);
                *(uint32_t*)&outl[(size_t)rbase * Nglob + col] = pack2(l0, l1);
                split_bf16(acc[mi][nf][2], h0, l0);
                split_bf16(acc[mi][nf][3], h1, l1);
                *(uint32_t*)&outh[(size_t)(rbase + 8) * Nglob + col] = pack2(h0, h1);
                *(uint32_t*)&outl[(size_t)(rbase + 8) * Nglob + col] = pack2(l0, l1);
            } else {
                float bx = 0.f, by = 0.f;
                if (bias) { bx = bias[col]; by = bias[col + 1]; }
                float2 v0 = { acc[mi][nf][0] + bx, acc[mi][nf][1] + by };
                float2 v1 = { acc[mi][nf][2] + bx, acc[mi][nf][3] + by };
                *(float2*)&Cmat[(size_t)rbase * Nglob + col]       = v0;
                *(float2*)&Cmat[(size_t)(rbase + 8) * Nglob + col] = v1;
            }
        }
    }
}

// ===========================================================================
// Tensor-core causal flash attention, bf16 hi/lo compensated.
// q-tile 128 x k-tile 64, 8 warps. K/V split into two cp.async groups:
// S-phase waits only on K (V streams in through S+softmax), PV-phase waits V.
// ===========================================================================
#define AP 144
#define Q_STAGE_L (128 * AP)           // 18432 (Qh at 0, Ql at Q_STAGE_L)
#define KV_T      (64 * AP)            // 9216: Kh 0 | Kl 9216 | Vh 18432 | Vl 27648

__global__ __launch_bounds__(256, 1)
void attn_mma(const __nv_bfloat16* __restrict__ Qh, const __nv_bfloat16* __restrict__ Ql,
              const __nv_bfloat16* __restrict__ Kh, const __nv_bfloat16* __restrict__ Kl,
              const __nv_bfloat16* __restrict__ Vh, const __nv_bfloat16* __restrict__ Vl,
              __nv_bfloat16* __restrict__ Ao_h, __nv_bfloat16* __restrict__ Ao_l)
{
    __shared__ char sm[2 * Q_STAGE_L];   // 36864 B
    const uint32_t sb = smem_u32(sm);

    const int tid  = threadIdx.x;
    const int lane = tid & 31;
    const int w    = tid >> 5;
    const int qt   = (int)gridDim.x - 1 - (int)blockIdx.x;   // big tiles first
    const int h    = blockIdx.y;
    const int b    = blockIdx.z;

    const int tq = lane >> 2;
    const int tr = lane & 3;
    const int a_row = (lane & 7) + ((lane >> 3) & 1) * 8;
    const int a_kb  = (lane >> 4);
    const int b_row = (lane & 7) + ((lane >> 4) & 1) * 8;
    const int b_kb  = (lane >> 3) & 1;

    // ---- stage Q hi/lo (128 rows x 64 bf16), preload frags to registers
    {
        const size_t qg0 = (size_t)(b * T_DIM + qt * 128) * C_DIM + h * DH_DIM;
#pragma unroll
        for (int k = 0; k < 4; k++) {
            int u = tid + k * 256;
            int r = u >> 3, c = u & 7;
            size_t ga = qg0 + (size_t)r * C_DIM + c * 8;
            uint32_t sa = (uint32_t)(r * AP + c * 16);
            CP_ASYNC16(sb + sa,             Qh + ga);
            CP_ASYNC16(sb + Q_STAGE_L + sa, Ql + ga);
        }
        CP_COMMIT();
        CP_WAIT0();
        __syncthreads();
    }
    uint32_t qfh[4][4], qfl[4][4];
#pragma unroll
    for (int ks = 0; ks < 4; ks++) {
        uint32_t ar = sb + (uint32_t)((w * 16 + a_row) * AP + ks * 32 + a_kb * 16);
        ldsm4(qfh[ks], ar);
        ldsm4(qfl[ks], ar + Q_STAGE_L);
    }
    __syncthreads();   // Q staging done; smem now reused for K/V

    float oacc[8][4];
#pragma unroll
    for (int nf = 0; nf < 8; nf++)
#pragma unroll
        for (int e = 0; e < 4; e++) oacc[nf][e] = 0.f;
    float m0 = -1e30f, m1 = -1e30f, l0 = 0.f, l1 = 0.f;

    const float SC = 0.18033688f;      // DH^-0.5 * log2(e)
    const size_t kvbase = (size_t)(b * T_DIM) * C_DIM + h * DH_DIM;
    const int ntiles = 2 * qt + 2;

    for (int kt = 0; kt < ntiles; kt++) {
        __syncthreads();               // previous tile fully consumed
        // group 1: K hi/lo
#pragma unroll
        for (int k = 0; k < 2; k++) {
            int u = tid + k * 256;
            int r = u >> 3, c = u & 7;
            size_t ga = kvbase + (size_t)(kt * 64 + r) * C_DIM + c * 8;
            uint32_t sa = (uint32_t)(r * AP + c * 16);
            CP_ASYNC16(sb + 0 * KV_T + sa, Kh + ga);
            CP_ASYNC16(sb + 1 * KV_T + sa, Kl + ga);
        }
        CP_COMMIT();
        // group 2: V hi/lo
#pragma unroll
        for (int k = 0; k < 2; k++) {
            int u = tid + k * 256;
            int r = u >> 3, c = u & 7;
            size_t ga = kvbase + (size_t)(kt * 64 + r) * C_DIM + c * 8;
            uint32_t sa = (uint32_t)(r * AP + c * 16);
            CP_ASYNC16(sb + 2 * KV_T + sa, Vh + ga);
            CP_ASYNC16(sb + 3 * KV_T + sa, Vl + ga);
        }
        CP_COMMIT();
        CP_WAIT1();                    // K resident; V still streaming
        __syncthreads();

        // ---- S = Q K^T (3-term)
        float sacc[8][4];
#pragma unroll
        for (int nf = 0; nf < 8; nf++)
#pragma unroll
            for (int e = 0; e < 4; e++) sacc[nf][e] = 0.f;

#pragma unroll
        for (int ks = 0; ks < 4; ks++) {
            uint32_t kh4[4][4], kl4[4][4];
#pragma unroll
            for (int p = 0; p < 4; p++) {
                uint32_t br = sb + (uint32_t)((p * 16 + b_row) * AP + ks * 32 + b_kb * 16);
                ldsm4(kh4[p], br);
                ldsm4(kl4[p], br + KV_T);
            }
#pragma unroll
            for (int p = 0; p < 4; p++) {
                mma16816(sacc[2 * p + 0], qfh[ks], &kh4[p][0]);
                mma16816(sacc[2 * p + 0], qfh[ks], &kl4[p][0]);
                mma16816(sacc[2 * p + 0], qfl[ks], &kh4[p][0]);
                mma16816(sacc[2 * p + 1], qfh[ks], &kh4[p][2]);
                mma16816(sacc[2 * p + 1], qfh[ks], &kl4[p][2]);
                mma16816(sacc[2 * p + 1], qfl[ks], &kh4[p][2]);
            }
        }

        // scale (base-2) + causal mask on diagonal tiles
        const bool need_mask = (kt >= 2 * qt);
#pragma unroll
        for (int nf = 0; nf < 8; nf++)
#pragma unroll
            for (int e = 0; e < 4; e++) {
                float s = sacc[nf][e] * SC;
                if (need_mask) {
                    int kg = kt * 64 + nf * 8 + 2 * tr + (e & 1);
                    int qg = qt * 128 + w * 16 + tq + ((e >> 1) << 3);
                    if (kg > qg) s = -1e30f;
                }
                sacc[nf][e] = s;
            }

        // row max (4-lane groups share a row)
        float mx0 = -1e30f, mx1 = -1e30f;
#pragma unroll
        for (int nf = 0; nf < 8; nf++) {
            mx0 = fmaxf(mx0, fmaxf(sacc[nf][0], sacc[nf][1]));
            mx1 = fmaxf(mx1, fmaxf(sacc[nf][2], sacc[nf][3]));
        }
        mx0 = fmaxf(mx0, __shfl_xor_sync(0xffffffffu, mx0, 1));
        mx0 = fmaxf(mx0, __shfl_xor_sync(0xffffffffu, mx0, 2));
        mx1 = fmaxf(mx1, __shfl_xor_sync(0xffffffffu, mx1, 1));
        mx1 = fmaxf(mx1, __shfl_xor_sync(0xffffffffu, mx1, 2));
        float mn0 = fmaxf(m0, mx0), mn1 = fmaxf(m1, mx1);
        float cr0 = exp2f(m0 - mn0), cr1 = exp2f(m1 - mn1);
        m0 = mn0; m1 = mn1;

        // exp + pack P as A-fragments (hi/lo)
        float rs0 = 0.f, rs1 = 0.f;
        uint32_t ph[4][4], pl[4][4];
#pragma unroll
        for (int kk = 0; kk < 4; kk++)
#pragma unroll
            for (int hh = 0; hh < 2; hh++) {
                int f = 2 * kk + hh;
                float e0 = exp2f(sacc[f][0] - mn0);
                float e1 = exp2f(sacc[f][1] - mn0);
                float e2 = exp2f(sacc[f][2] - mn1);
                float e3 = exp2f(sacc[f][3] - mn1);
                rs0 += e0 + e1;
                rs1 += e2 + e3;
                __nv_bfloat16 h0, q0, h1, q1, h2, q2, h3, q3;
                split_bf16(e0, h0, q0);
                split_bf16(e1, h1, q1);
                split_bf16(e2, h2, q2);
                split_bf16(e3, h3, q3);
                ph[kk][hh * 2 + 0] = pack2(h0, h1);
                ph[kk][hh * 2 + 1] = pack2(h2, h3);
                pl[kk][hh * 2 + 0] = pack2(q0, q1);
                pl[kk][hh * 2 + 1] = pack2(q2, q3);
            }
        rs0 += __shfl_xor_sync(0xffffffffu, rs0, 1);
        rs0 += __shfl_xor_sync(0xffffffffu, rs0, 2);
        rs1 += __shfl_xor_sync(0xffffffffu, rs1, 1);
        rs1 += __shfl_xor_sync(0xffffffffu, rs1, 2);
        l0 = l0 * cr0 + rs0;
        l1 = l1 * cr1 + rs1;
#pragma unroll
        for (int nf = 0; nf < 8; nf++) {
            oacc[nf][0] *= cr0;
            oacc[nf][1] *= cr0;
            oacc[nf][2] *= cr1;
            oacc[nf][3] *= cr1;
        }

        // ---- O += P V (3-term), V loaded transposed
        CP_WAIT0();                    // V group complete
        __syncthreads();               // block-wide visibility of V
#pragma unroll
        for (int kk = 0; kk < 4; kk++)
#pragma unroll
            for (int p = 0; p < 4; p++) {
                uint32_t va = sb + 2 * KV_T
                    + (uint32_t)((kk * 16 + (lane & 7) + ((lane >> 3) & 1) * 8) * AP
                                 + (p * 16 + (lane >> 4) * 8) * 2);
                uint32_t vh4[4], vl4[4];
                ldsm4t(vh4, va);
                ldsm4t(vl4, va + KV_T);
                mma16816(oacc[2 * p + 0], ph[kk], &vh4[0]);
                mma16816(oacc[2 * p + 0], ph[kk], &vl4[0]);
                mma16816(oacc[2 * p + 0], pl[kk], &vh4[0]);
                mma16816(oacc[2 * p + 1], ph[kk], &vh4[2]);
                mma16816(oacc[2 * p + 1], ph[kk], &vl4[2]);
                mma16816(oacc[2 * p + 1], pl[kk], &vh4[2]);
            }
    }

    // epilogue: normalize, split hi/lo, write [B,T, h*64+d]
    const float inv0 = 1.f / l0;
    const float inv1 = 1.f / l1;
    const size_t r0 = (size_t)(b * T_DIM + qt * 128 + w * 16 + tq);
    const size_t r1 = r0 + 8;
#pragma unroll
    for (int nf = 0; nf < 8; nf++) {
        int col = h * DH_DIM + nf * 8 + 2 * tr;
        __nv_bfloat16 h0, q0, h1, q1;
        split_bf16(oacc[nf][0] * inv0, h0, q0);
        split_bf16(oacc[nf][1] * inv0, h1, q1);
        *(uint32_t*)&Ao_h[r0 * C_DIM + col] = pack2(h0, h1);
        *(uint32_t*)&Ao_l[r0 * C_DIM + col] = pack2(q0, q1);
        split_bf16(oacc[nf][2] * inv1, h0, q0);
        split_bf16(oacc[nf][3] * inv1, h1, q1);
        *(uint32_t*)&Ao_h[r1 * C_DIM + col] = pack2(h0, h1);
        *(uint32_t*)&Ao_l[r1 * C_DIM + col] = pack2(q0, q1);
    }
}

// ===========================================================================
// Launch
// ===========================================================================
extern "C" void kernel_launch(void* const* d_in, const int* in_sizes, int n_in,
                              void* d_out, int out_size)
{
    (void)in_sizes; (void)n_in; (void)out_size;
    const float* x  = (const float*)d_in[0];
    const float* Wq = (const float*)d_in[1];
    const float* Wk = (const float*)d_in[2];
    const float* Wv = (const float*)d_in[3];
    const float* Wo = (const float*)d_in[4];
    const float* bo = (const float*)d_in[5];
    float* out = (float*)d_out;

    __nv_bfloat16 *pXh, *pXl, *pAh, *pAl;
    __nv_bfloat16 *pQh, *pQl, *pKh, *pKl, *pVh, *pVl;
    __nv_bfloat16 *pWqh, *pWql, *pWkh, *pWkl, *pWvh, *pWvl, *pWoh, *pWol;
    cudaGetSymbolAddress((void**)&pXh,  g_Xh);
    cudaGetSymbolAddress((void**)&pXl,  g_Xl);
    cudaGetSymbolAddress((void**)&pAh,  g_Ah);
    cudaGetSymbolAddress((void**)&pAl,  g_Al);
    cudaGetSymbolAddress((void**)&pQh,  g_Qh);
    cudaGetSymbolAddress((void**)&pQl,  g_Ql);
    cudaGetSymbolAddress((void**)&pKh,  g_Kh);
    cudaGetSymbolAddress((void**)&pKl,  g_Kl);
    cudaGetSymbolAddress((void**)&pVh,  g_Vh);
    cudaGetSymbolAddress((void**)&pVl,  g_Vl);
    cudaGetSymbolAddress((void**)&pWqh, g_Wqh);
    cudaGetSymbolAddress((void**)&pWql, g_Wql);
    cudaGetSymbolAddress((void**)&pWkh, g_Wkh);
    cudaGetSymbolAddress((void**)&pWkl, g_Wkl);
    cudaGetSymbolAddress((void**)&pWvh, g_Wvh);
    cudaGetSymbolAddress((void**)&pWvl, g_Wvl);
    cudaGetSymbolAddress((void**)&pWoh, g_Woh);
    cudaGetSymbolAddress((void**)&pWol, g_Wol);

    // 1. splits / weight prep
    prep_weights<<<(C_DIM * C_DIM) / 256, 256>>>(Wq, Wk, Wv, Wo);
    split_x<<<(M_DIM * C_DIM) / 256, 256>>>(x);

    // 2. QKV projections -> bf16 hi/lo directly
    dim3 gg(C_DIM / 128, M_DIM / 128);   // (8, 64)
    gemm_mma<<<gg, 256>>>(pXh, pXl, pWqh, pWql, nullptr, nullptr, pQh, pQl, C_DIM, C_DIM);
    gemm_mma<<<gg, 256>>>(pXh, pXl, pWkh, pWkl, nullptr, nullptr, pKh, pKl, C_DIM, C_DIM);
    gemm_mma<<<gg, 256>>>(pXh, pXl, pWvh, pWvl, nullptr, nullptr, pVh, pVl, C_DIM, C_DIM);

    // 3. tensor-core causal flash attention -> bf16 hi/lo
    attn_mma<<<dim3(T_DIM / 128, H_DIM, B_DIM), 256>>>(pQh, pQl, pKh, pKl, pVh, pVl, pAh, pAl);

    // 4. output projection (fp32 out + bias)
    gemm_mma<<<gg, 256>>>(pAh, pAl, pWoh, pWol, out, bo, nullptr, nullptr, C_DIM, C_DIM);
}

// round 10
// speedup vs baseline: 1.1115x; 1.1115x over previous
#include <cuda_runtime.h>
#include <cuda_bf16.h>
#include <cstdint>

// Problem constants
#define C_DIM 1024
#define B_DIM 4
#define T_DIM 2048
#define H_DIM 16
#define DH_DIM 64
#define M_DIM (B_DIM * T_DIM)   // 8192

// ===========================================================================
// Scratch (__device__ globals; no cudaMalloc allowed)
// ===========================================================================
__device__ __nv_bfloat16  g_Xh [M_DIM * C_DIM];   // x hi/lo split
__device__ __nv_bfloat16  g_Xl [M_DIM * C_DIM];
__device__ __nv_bfloat16  g_Qh [M_DIM * C_DIM], g_Ql [M_DIM * C_DIM];
__device__ __nv_bfloat16  g_Kh [M_DIM * C_DIM], g_Kl [M_DIM * C_DIM];
__device__ __nv_bfloat16  g_Vh [M_DIM * C_DIM], g_Vl [M_DIM * C_DIM];
__device__ __nv_bfloat16  g_Ah [M_DIM * C_DIM], g_Al [M_DIM * C_DIM];
// weights as [N][K] bf16 hi/lo (B operand of mma .col = K-major [N,K] rows)
__device__ __nv_bfloat16  g_Wqh[C_DIM * C_DIM], g_Wql[C_DIM * C_DIM];
__device__ __nv_bfloat16  g_Wkh[C_DIM * C_DIM], g_Wkl[C_DIM * C_DIM];
__device__ __nv_bfloat16  g_Wvh[C_DIM * C_DIM], g_Wvl[C_DIM * C_DIM];
__device__ __nv_bfloat16  g_Woh[C_DIM * C_DIM], g_Wol[C_DIM * C_DIM];

__device__ __forceinline__ void split_bf16(float v, __nv_bfloat16& h, __nv_bfloat16& l) {
    __nv_bfloat16 hi = __float2bfloat16(v);
    h = hi;
    l = __float2bfloat16(v - __bfloat162float(hi));
}
__device__ __forceinline__ uint32_t pack2(__nv_bfloat16 lo, __nv_bfloat16 hi) {
    __nv_bfloat162 t(lo, hi);
    return reinterpret_cast<uint32_t&>(t);
}

// ---------------------------------------------------------------------------
// Weight prep: [H,C,DH] -> [n=h*64+d][c] bf16 hi/lo; Wo [j][c] is already [N][K].
// ---------------------------------------------------------------------------
__global__ void prep_weights(const float* __restrict__ Wq,
                             const float* __restrict__ Wk,
                             const float* __restrict__ Wv,
                             const float* __restrict__ Wo)
{
    int i = blockIdx.x * blockDim.x + threadIdx.x;   // i = n*1024 + c
    int n = i >> 10;
    int c = i & 1023;
    int h = n >> 6;
    int d = n & 63;
    int src = (h << 16) + (c << 6) + d;              // h*C*DH + c*DH + d
    split_bf16(Wq[src], g_Wqh[i], g_Wql[i]);
    split_bf16(Wk[src], g_Wkh[i], g_Wkl[i]);
    split_bf16(Wv[src], g_Wvh[i], g_Wvl[i]);
    split_bf16(Wo[i],   g_Woh[i], g_Wol[i]);
}

__global__ void split_x(const float* __restrict__ x)
{
    int i = blockIdx.x * blockDim.x + threadIdx.x;
    split_bf16(x[i], g_Xh[i], g_Xl[i]);
}

// ===========================================================================
// PTX wrappers (all plain sm_80+ — assemble under compute_103)
// ===========================================================================
__device__ __forceinline__ uint32_t smem_u32(const void* p) {
    uint32_t a;
    asm("{ .reg .u64 t; cvta.to.shared.u64 t, %1; cvt.u32.u64 %0, t; }"
        : "=r"(a) : "l"(p));
    return a;
}
__device__ __forceinline__ void ldsm4(uint32_t* r, uint32_t addr) {
    asm volatile("ldmatrix.sync.aligned.m8n8.x4.shared.b16 {%0,%1,%2,%3}, [%4];"
                 : "=r"(r[0]), "=r"(r[1]), "=r"(r[2]), "=r"(r[3]) : "r"(addr));
}
__device__ __forceinline__ void ldsm4t(uint32_t* r, uint32_t addr) {
    asm volatile("ldmatrix.sync.aligned.m8n8.x4.trans.shared.b16 {%0,%1,%2,%3}, [%4];"
                 : "=r"(r[0]), "=r"(r[1]), "=r"(r[2]), "=r"(r[3]) : "r"(addr));
}
__device__ __forceinline__ void mma16816(float* c, const uint32_t* a, const uint32_t* b) {
    asm volatile("mma.sync.aligned.m16n8k16.row.col.f32.bf16.bf16.f32 "
                 "{%0,%1,%2,%3}, {%4,%5,%6,%7}, {%8,%9}, {%0,%1,%2,%3};"
                 : "+f"(c[0]), "+f"(c[1]), "+f"(c[2]), "+f"(c[3])
                 : "r"(a[0]), "r"(a[1]), "r"(a[2]), "r"(a[3]),
                   "r"(b[0]), "r"(b[1]));
}
#define CP_ASYNC16(saddr, gptr) \
    asm volatile("cp.async.cg.shared.global [%0], [%1], 16;" \
                 :: "r"(saddr), "l"(gptr) : "memory")
#define CP_COMMIT()  asm volatile("cp.async.commit_group;" ::: "memory")
#define CP_WAIT0()   asm volatile("cp.async.wait_group 0;" ::: "memory")
#define CP_WAIT1()   asm volatile("cp.async.wait_group 1;" ::: "memory")

// ===========================================================================
// bf16 hi/lo GEMM, 2-stage double-buffered, K-chunk 32 (R8 geometry + pipeline).
// Block 128x128, 8 warps (4m x 2n), warp tile 32x64, pitch 80B (conflict-free
// ldmatrix: start banks 20r mod 32). Stage = 4 tiles x 10240B = 40960B;
// 2 stages = 81920B DYNAMIC shared (attribute opt-in). 2 CTAs/SM.
// Per chunk: 2 syncs, chunk ch+1 streams (wait_group 1) during compute of ch.
// Output: fp32 (+bias) if outh==null, else bf16 hi/lo split pair.
// ===========================================================================
#define PITCH   80
#define TILE_B  (128 * PITCH)          // 10240 bytes per tile
#define GSTG    (4 * TILE_B)           // 40960 per stage
#define GSM_TOT (2 * GSTG)             // 81920 dynamic
#define OA_H    0
#define OA_L    (TILE_B)
#define OB_H    (2 * TILE_B)
#define OB_L    (3 * TILE_B)

__global__ __launch_bounds__(256, 2)
void gemm_mma(const __nv_bfloat16* __restrict__ Ahp, const __nv_bfloat16* __restrict__ Alp,
              const __nv_bfloat16* __restrict__ Bhp, const __nv_bfloat16* __restrict__ Blp,
              float* __restrict__ Cmat, const float* __restrict__ bias,
              __nv_bfloat16* __restrict__ outh, __nv_bfloat16* __restrict__ outl,
              int Nglob, int Kglob)
{
    extern __shared__ char smdyn[];
    const uint32_t sb = smem_u32(smdyn);

    const int tid  = threadIdx.x;
    const int lane = tid & 31;
    const int wid  = tid >> 5;
    const int wm   = wid & 3;
    const int wn   = wid >> 2;

    const int row0 = blockIdx.y * 128;
    const int col0 = blockIdx.x * 128;

    // gmem load mapping: thread covers 16B blocks u = tid, tid+256 of each tile
    const int r0g = tid >> 2;                 // row of block u0 (0..63)
    const int c0g = tid & 3;                  // 16B col of block u0 (0..3)
    const __nv_bfloat16* pAh0 = Ahp + (size_t)(row0 + r0g) * Kglob + c0g * 8;
    const __nv_bfloat16* pAl0 = Alp + (size_t)(row0 + r0g) * Kglob + c0g * 8;
    const __nv_bfloat16* pBh0 = Bhp + (size_t)(col0 + r0g) * Kglob + c0g * 8;
    const __nv_bfloat16* pBl0 = Blp + (size_t)(col0 + r0g) * Kglob + c0g * 8;
    const size_t rowStep = (size_t)64 * Kglob;
    const uint32_t s0 = (uint32_t)(r0g * PITCH + c0g * 16);
    const uint32_t s1 = s0 + 64 * PITCH;

    const int a_row = (lane & 7) + ((lane >> 3) & 1) * 8;
    const int a_kb  = (lane >> 4);
    const int b_row = (lane & 7) + ((lane >> 4) & 1) * 8;
    const int b_kb  = (lane >> 3) & 1;

    float acc[2][8][4];
#pragma unroll
    for (int mi = 0; mi < 2; mi++)
#pragma unroll
        for (int nf = 0; nf < 8; nf++)
#pragma unroll
            for (int e = 0; e < 4; e++) acc[mi][nf][e] = 0.f;

    const int NCH = Kglob >> 5;        // chunks of 32

    // prologue: chunk 0 -> stage 0
    {
        const uint32_t base = sb;
        CP_ASYNC16(base + OA_H + s0, pAh0);
        CP_ASYNC16(base + OA_H + s1, pAh0 + rowStep);
        CP_ASYNC16(base + OA_L + s0, pAl0);
        CP_ASYNC16(base + OA_L + s1, pAl0 + rowStep);
        CP_ASYNC16(base + OB_H + s0, pBh0);
        CP_ASYNC16(base + OB_H + s1, pBh0 + rowStep);
        CP_ASYNC16(base + OB_L + s0, pBl0);
        CP_ASYNC16(base + OB_L + s1, pBl0 + rowStep);
        CP_COMMIT();
    }

    for (int ch = 0; ch < NCH; ch++) {
        const int buf = ch & 1;
        if (ch + 1 < NCH) {            // stream chunk ch+1 into the other stage
            const int k1 = (ch + 1) << 5;
            const uint32_t base = sb + (buf ^ 1) * GSTG;
            CP_ASYNC16(base + OA_H + s0, pAh0 + k1);
            CP_ASYNC16(base + OA_H + s1, pAh0 + rowStep + k1);
            CP_ASYNC16(base + OA_L + s0, pAl0 + k1);
            CP_ASYNC16(base + OA_L + s1, pAl0 + rowStep + k1);
            CP_ASYNC16(base + OB_H + s0, pBh0 + k1);
            CP_ASYNC16(base + OB_H + s1, pBh0 + rowStep + k1);
            CP_ASYNC16(base + OB_L + s0, pBl0 + k1);
            CP_ASYNC16(base + OB_L + s1, pBl0 + rowStep + k1);
            CP_COMMIT();
            CP_WAIT1();                // chunk ch resident; ch+1 in flight
        } else {
            CP_WAIT0();
        }
        __syncthreads();

        const uint32_t base = sb + buf * GSTG;
#pragma unroll
        for (int ks = 0; ks < 2; ks++) {
            uint32_t ah[2][4], al[2][4], bh[4][4], bl[4][4];
#pragma unroll
            for (int mi = 0; mi < 2; mi++) {
                uint32_t ar = base + (uint32_t)((wm * 32 + mi * 16 + a_row) * PITCH
                                                + (2 * ks + a_kb) * 16);
                ldsm4(ah[mi], ar + OA_H);
                ldsm4(al[mi], ar + OA_L);
            }
#pragma unroll
            for (int p = 0; p < 4; p++) {
                uint32_t br = base + (uint32_t)((wn * 64 + p * 16 + b_row) * PITCH
                                                + (2 * ks + b_kb) * 16);
                ldsm4(bh[p], br + OB_H);
                ldsm4(bl[p], br + OB_L);
            }
#pragma unroll
            for (int mi = 0; mi < 2; mi++)
#pragma unroll
                for (int p = 0; p < 4; p++) {
                    mma16816(acc[mi][2 * p + 0], ah[mi], &bh[p][0]);
                    mma16816(acc[mi][2 * p + 0], ah[mi], &bl[p][0]);
                    mma16816(acc[mi][2 * p + 0], al[mi], &bh[p][0]);
                    mma16816(acc[mi][2 * p + 1], ah[mi], &bh[p][2]);
                    mma16816(acc[mi][2 * p + 1], ah[mi], &bl[p][2]);
                    mma16816(acc[mi][2 * p + 1], al[mi], &bh[p][2]);
                }
        }
        __syncthreads();               // stage `buf` free for iter ch+1's writes
    }

    const int tq = lane >> 2;
    const int tr = lane & 3;
#pragma unroll
    for (int mi = 0; mi < 2; mi++) {
        int rbase = row0 + wm * 32 + mi * 16 + tq;
#pragma unroll
        for (int nf = 0; nf < 8; nf++) {
            int col = col0 + wn * 64 + nf * 8 + tr * 2;
            if (outh) {
                __nv_bfloat16 h0, l0, h1, l1;
                split_bf16(acc[mi][nf][0], h0, l0);
                split_bf16(acc[mi][nf][1], h1, l1);
                *(uint32_t*)&outh[(size_t)rbase * Nglob + col] = pack2(h0, h1);
                *(uint32_t*)&outl[(size_t)rbase * Nglob + col] = pack2(l0, l1);
                split_bf16(acc[mi][nf][2], h0, l0);
                split_bf16(acc[mi][nf][3], h1, l1);
                *(uint32_t*)&outh[(size_t)(rbase + 8) * Nglob + col] = pack2(h0, h1);
                *(uint32_t*)&outl[(size_t)(rbase + 8) * Nglob + col] = pack2(l0, l1);
            } else {
                float bx = 0.f, by = 0.f;
                if (bias) { bx = bias[col]; by = bias[col + 1]; }
                float2 v0 = { acc[mi][nf][0] + bx, acc[mi][nf][1] + by };
                float2 v1 = { acc[mi][nf][2] + bx, acc[mi][nf][3] + by };
                *(float2*)&Cmat[(size_t)rbase * Nglob + col]       = v0;
                *(float2*)&Cmat[(size_t)(rbase + 8) * Nglob + col] = v1;
            }
        }
    }
}

// ===========================================================================
// Tensor-core causal flash attention, bf16 hi/lo compensated (R9 version:
// K/V in separate cp.async groups; V streams through S+softmax phase).
// q-tile 128 x k-tile 64, 8 warps. Pitch 144B smem, 36KB static.
// ===========================================================================
#define AP 144
#define Q_STAGE_L (128 * AP)           // 18432 (Qh at 0, Ql at Q_STAGE_L)
#define KV_T      (64 * AP)            // 9216: Kh 0 | Kl 9216 | Vh 18432 | Vl 27648

__global__ __launch_bounds__(256, 1)
void attn_mma(const __nv_bfloat16* __restrict__ Qh, const __nv_bfloat16* __restrict__ Ql,
              const __nv_bfloat16* __restrict__ Kh, const __nv_bfloat16* __restrict__ Kl,
              const __nv_bfloat16* __restrict__ Vh, const __nv_bfloat16* __restrict__ Vl,
              __nv_bfloat16* __restrict__ Ao_h, __nv_bfloat16* __restrict__ Ao_l)
{
    __shared__ char sm[2 * Q_STAGE_L];   // 36864 B
    const uint32_t sb = smem_u32(sm);

    const int tid  = threadIdx.x;
    const int lane = tid & 31;
    const int w    = tid >> 5;
    const int qt   = (int)gridDim.x - 1 - (int)blockIdx.x;   // big tiles first
    const int h    = blockIdx.y;
    const int b    = blockIdx.z;

    const int tq = lane >> 2;
    const int tr = lane & 3;
    const int a_row = (lane & 7) + ((lane >> 3) & 1) * 8;
    const int a_kb  = (lane >> 4);
    const int b_row = (lane & 7) + ((lane >> 4) & 1) * 8;
    const int b_kb  = (lane >> 3) & 1;

    // ---- stage Q hi/lo (128 rows x 64 bf16), preload frags to registers
    {
        const size_t qg0 = (size_t)(b * T_DIM + qt * 128) * C_DIM + h * DH_DIM;
#pragma unroll
        for (int k = 0; k < 4; k++) {
            int u = tid + k * 256;
            int r = u >> 3, c = u & 7;
            size_t ga = qg0 + (size_t)r * C_DIM + c * 8;
            uint32_t sa = (uint32_t)(r * AP + c * 16);
            CP_ASYNC16(sb + sa,             Qh + ga);
            CP_ASYNC16(sb + Q_STAGE_L + sa, Ql + ga);
        }
        CP_COMMIT();
        CP_WAIT0();
        __syncthreads();
    }
    uint32_t qfh[4][4], qfl[4][4];
#pragma unroll
    for (int ks = 0; ks < 4; ks++) {
        uint32_t ar = sb + (uint32_t)((w * 16 + a_row) * AP + ks * 32 + a_kb * 16);
        ldsm4(qfh[ks], ar);
        ldsm4(qfl[ks], ar + Q_STAGE_L);
    }
    __syncthreads();   // Q staging done; smem now reused for K/V

    float oacc[8][4];
#pragma unroll
    for (int nf = 0; nf < 8; nf++)
#pragma unroll
        for (int e = 0; e < 4; e++) oacc[nf][e] = 0.f;
    float m0 = -1e30f, m1 = -1e30f, l0 = 0.f, l1 = 0.f;

    const float SC = 0.18033688f;      // DH^-0.5 * log2(e)
    const size_t kvbase = (size_t)(b * T_DIM) * C_DIM + h * DH_DIM;
    const int ntiles = 2 * qt + 2;

    for (int kt = 0; kt < ntiles; kt++) {
        __syncthreads();               // previous tile fully consumed
        // group 1: K hi/lo
#pragma unroll
        for (int k = 0; k < 2; k++) {
            int u = tid + k * 256;
            int r = u >> 3, c = u & 7;
            size_t ga = kvbase + (size_t)(kt * 64 + r) * C_DIM + c * 8;
            uint32_t sa = (uint32_t)(r * AP + c * 16);
            CP_ASYNC16(sb + 0 * KV_T + sa, Kh + ga);
            CP_ASYNC16(sb + 1 * KV_T + sa, Kl + ga);
        }
        CP_COMMIT();
        // group 2: V hi/lo
#pragma unroll
        for (int k = 0; k < 2; k++) {
            int u = tid + k * 256;
            int r = u >> 3, c = u & 7;
            size_t ga = kvbase + (size_t)(kt * 64 + r) * C_DIM + c * 8;
            uint32_t sa = (uint32_t)(r * AP + c * 16);
            CP_ASYNC16(sb + 2 * KV_T + sa, Vh + ga);
            CP_ASYNC16(sb + 3 * KV_T + sa, Vl + ga);
        }
        CP_COMMIT();
        CP_WAIT1();                    // K resident; V still streaming
        __syncthreads();

        // ---- S = Q K^T (3-term)
        float sacc[8][4];
#pragma unroll
        for (int nf = 0; nf < 8; nf++)
#pragma unroll
            for (int e = 0; e < 4; e++) sacc[nf][e] = 0.f;

#pragma unroll
        for (int ks = 0; ks < 4; ks++) {
            uint32_t kh4[4][4], kl4[4][4];
#pragma unroll
            for (int p = 0; p < 4; p++) {
                uint32_t br = sb + (uint32_t)((p * 16 + b_row) * AP + ks * 32 + b_kb * 16);
                ldsm4(kh4[p], br);
                ldsm4(kl4[p], br + KV_T);
            }
#pragma unroll
            for (int p = 0; p < 4; p++) {
                mma16816(sacc[2 * p + 0], qfh[ks], &kh4[p][0]);
                mma16816(sacc[2 * p + 0], qfh[ks], &kl4[p][0]);
                mma16816(sacc[2 * p + 0], qfl[ks], &kh4[p][0]);
                mma16816(sacc[2 * p + 1], qfh[ks], &kh4[p][2]);
                mma16816(sacc[2 * p + 1], qfh[ks], &kl4[p][2]);
                mma16816(sacc[2 * p + 1], qfl[ks], &kh4[p][2]);
            }
        }

        // scale (base-2) + causal mask on diagonal tiles
        const bool need_mask = (kt >= 2 * qt);
#pragma unroll
        for (int nf = 0; nf < 8; nf++)
#pragma unroll
            for (int e = 0; e < 4; e++) {
                float s = sacc[nf][e] * SC;
                if (need_mask) {
                    int kg = kt * 64 + nf * 8 + 2 * tr + (e & 1);
                    int qg = qt * 128 + w * 16 + tq + ((e >> 1) << 3);
                    if (kg > qg) s = -1e30f;
                }
                sacc[nf][e] = s;
            }

        // row max (4-lane groups share a row)
        float mx0 = -1e30f, mx1 = -1e30f;
#pragma unroll
        for (int nf = 0; nf < 8; nf++) {
            mx0 = fmaxf(mx0, fmaxf(sacc[nf][0], sacc[nf][1]));
            mx1 = fmaxf(mx1, fmaxf(sacc[nf][2], sacc[nf][3]));
        }
        mx0 = fmaxf(mx0, __shfl_xor_sync(0xffffffffu, mx0, 1));
        mx0 = fmaxf(mx0, __shfl_xor_sync(0xffffffffu, mx0, 2));
        mx1 = fmaxf(mx1, __shfl_xor_sync(0xffffffffu, mx1, 1));
        mx1 = fmaxf(mx1, __shfl_xor_sync(0xffffffffu, mx1, 2));
        float mn0 = fmaxf(m0, mx0), mn1 = fmaxf(m1, mx1);
        float cr0 = exp2f(m0 - mn0), cr1 = exp2f(m1 - mn1);
        m0 = mn0; m1 = mn1;

        // exp + pack P as A-fragments (hi/lo)
        float rs0 = 0.f, rs1 = 0.f;
        uint32_t ph[4][4], pl[4][4];
#pragma unroll
        for (int kk = 0; kk < 4; kk++)
#pragma unroll
            for (int hh = 0; hh < 2; hh++) {
                int f = 2 * kk + hh;
                float e0 = exp2f(sacc[f][0] - mn0);
                float e1 = exp2f(sacc[f][1] - mn0);
                float e2 = exp2f(sacc[f][2] - mn1);
                float e3 = exp2f(sacc[f][3] - mn1);
                rs0 += e0 + e1;
                rs1 += e2 + e3;
                __nv_bfloat16 h0, q0, h1, q1, h2, q2, h3, q3;
                split_bf16(e0, h0, q0);
                split_bf16(e1, h1, q1);
                split_bf16(e2, h2, q2);
                split_bf16(e3, h3, q3);
                ph[kk][hh * 2 + 0] = pack2(h0, h1);
                ph[kk][hh * 2 + 1] = pack2(h2, h3);
                pl[kk][hh * 2 + 0] = pack2(q0, q1);
                pl[kk][hh * 2 + 1] = pack2(q2, q3);
            }
        rs0 += __shfl_xor_sync(0xffffffffu, rs0, 1);
        rs0 += __shfl_xor_sync(0xffffffffu, rs0, 2);
        rs1 += __shfl_xor_sync(0xffffffffu, rs1, 1);
        rs1 += __shfl_xor_sync(0xffffffffu, rs1, 2);
        l0 = l0 * cr0 + rs0;
        l1 = l1 * cr1 + rs1;
#pragma unroll
        for (int nf = 0; nf < 8; nf++) {
            oacc[nf][0] *= cr0;
            oacc[nf][1] *= cr0;
            oacc[nf][2] *= cr1;
            oacc[nf][3] *= cr1;
        }

        // ---- O += P V (3-term), V loaded transposed
        CP_WAIT0();                    // V group complete
        __syncthreads();               // block-wide visibility of V
#pragma unroll
        for (int kk = 0; kk < 4; kk++)
#pragma unroll
            for (int p = 0; p < 4; p++) {
                uint32_t va = sb + 2 * KV_T
                    + (uint32_t)((kk * 16 + (lane & 7) + ((lane >> 3) & 1) * 8) * AP
                                 + (p * 16 + (lane >> 4) * 8) * 2);
                uint32_t vh4[4], vl4[4];
                ldsm4t(vh4, va);
                ldsm4t(vl4, va + KV_T);
                mma16816(oacc[2 * p + 0], ph[kk], &vh4[0]);
                mma16816(oacc[2 * p + 0], ph[kk], &vl4[0]);
                mma16816(oacc[2 * p + 0], pl[kk], &vh4[0]);
                mma16816(oacc[2 * p + 1], ph[kk], &vh4[2]);
                mma16816(oacc[2 * p + 1], ph[kk], &vl4[2]);
                mma16816(oacc[2 * p + 1], pl[kk], &vh4[2]);
            }
    }

    // epilogue: normalize, split hi/lo, write [B,T, h*64+d]
    const float inv0 = 1.f / l0;
    const float inv1 = 1.f / l1;
    const size_t r0 = (size_t)(b * T_DIM + qt * 128 + w * 16 + tq);
    const size_t r1 = r0 + 8;
#pragma unroll
    for (int nf = 0; nf < 8; nf++) {
        int col = h * DH_DIM + nf * 8 + 2 * tr;
        __nv_bfloat16 h0, q0, h1, q1;
        split_bf16(oacc[nf][0] * inv0, h0, q0);
        split_bf16(oacc[nf][1] * inv0, h1, q1);
        *(uint32_t*)&Ao_h[r0 * C_DIM + col] = pack2(h0, h1);
        *(uint32_t*)&Ao_l[r0 * C_DIM + col] = pack2(q0, q1);
        split_bf16(oacc[nf][2] * inv1, h0, q0);
        split_bf16(oacc[nf][3] * inv1, h1, q1);
        *(uint32_t*)&Ao_h[r1 * C_DIM + col] = pack2(h0, h1);
        *(uint32_t*)&Ao_l[r1 * C_DIM + col] = pack2(q0, q1);
    }
}

// ===========================================================================
// Launch
// ===========================================================================
extern "C" void kernel_launch(void* const* d_in, const int* in_sizes, int n_in,
                              void* d_out, int out_size)
{
    (void)in_sizes; (void)n_in; (void)out_size;
    const float* x  = (const float*)d_in[0];
    const float* Wq = (const float*)d_in[1];
    const float* Wk = (const float*)d_in[2];
    const float* Wv = (const float*)d_in[3];
    const float* Wo = (const float*)d_in[4];
    const float* bo = (const float*)d_in[5];
    float* out = (float*)d_out;

    __nv_bfloat16 *pXh, *pXl, *pAh, *pAl;
    __nv_bfloat16 *pQh, *pQl, *pKh, *pKl, *pVh, *pVl;
    __nv_bfloat16 *pWqh, *pWql, *pWkh, *pWkl, *pWvh, *pWvl, *pWoh, *pWol;
    cudaGetSymbolAddress((void**)&pXh,  g_Xh);
    cudaGetSymbolAddress((void**)&pXl,  g_Xl);
    cudaGetSymbolAddress((void**)&pAh,  g_Ah);
    cudaGetSymbolAddress((void**)&pAl,  g_Al);
    cudaGetSymbolAddress((void**)&pQh,  g_Qh);
    cudaGetSymbolAddress((void**)&pQl,  g_Ql);
    cudaGetSymbolAddress((void**)&pKh,  g_Kh);
    cudaGetSymbolAddress((void**)&pKl,  g_Kl);
    cudaGetSymbolAddress((void**)&pVh,  g_Vh);
    cudaGetSymbolAddress((void**)&pVl,  g_Vl);
    cudaGetSymbolAddress((void**)&pWqh, g_Wqh);
    cudaGetSymbolAddress((void**)&pWql, g_Wql);
    cudaGetSymbolAddress((void**)&pWkh, g_Wkh);
    cudaGetSymbolAddress((void**)&pWkl, g_Wkl);
    cudaGetSymbolAddress((void**)&pWvh, g_Wvh);
    cudaGetSymbolAddress((void**)&pWvl, g_Wvl);
    cudaGetSymbolAddress((void**)&pWoh, g_Woh);
    cudaGetSymbolAddress((void**)&pWol, g_Wol);

    cudaFuncSetAttribute(gemm_mma, cudaFuncAttributeMaxDynamicSharedMemorySize, GSM_TOT);

    // 1. splits / weight prep
    prep_weights<<<(C_DIM * C_DIM) / 256, 256>>>(Wq, Wk, Wv, Wo);
    split_x<<<(M_DIM * C_DIM) / 256, 256>>>(x);

    // 2. QKV projections -> bf16 hi/lo directly
    dim3 gg(C_DIM / 128, M_DIM / 128);   // (8, 64)
    gemm_mma<<<gg, 256, GSM_TOT>>>(pXh, pXl, pWqh, pWql, nullptr, nullptr, pQh, pQl, C_DIM, C_DIM);
    gemm_mma<<<gg, 256, GSM_TOT>>>(pXh, pXl, pWkh, pWkl, nullptr, nullptr, pKh, pKl, C_DIM, C_DIM);
    gemm_mma<<<gg, 256, GSM_TOT>>>(pXh, pXl, pWvh, pWvl, nullptr, nullptr, pVh, pVl, C_DIM, C_DIM);

    // 3. tensor-core causal flash attention -> bf16 hi/lo
    attn_mma<<<dim3(T_DIM / 128, H_DIM, B_DIM), 256>>>(pQh, pQl, pKh, pKl, pVh, pVl, pAh, pAl);

    // 4. output projection (fp32 out + bias)
    gemm_mma<<<gg, 256, GSM_TOT>>>(pAh, pAl, pWoh, pWol, out, bo, nullptr, nullptr, C_DIM, C_DIM);
}

// round 11
// speedup vs baseline: 1.1692x; 1.0519x over previous
#include <cuda_runtime.h>
#include <cuda_bf16.h>
#include <cstdint>

// Problem constants
#define C_DIM 1024
#define B_DIM 4
#define T_DIM 2048
#define H_DIM 16
#define DH_DIM 64
#define M_DIM (B_DIM * T_DIM)   // 8192

// ===========================================================================
// Scratch (__device__ globals; no cudaMalloc allowed)
// ===========================================================================
__device__ __nv_bfloat16  g_Xh [M_DIM * C_DIM];   // x hi/lo split
__device__ __nv_bfloat16  g_Xl [M_DIM * C_DIM];
__device__ __nv_bfloat16  g_Qh [M_DIM * C_DIM], g_Ql [M_DIM * C_DIM];
__device__ __nv_bfloat16  g_Kh [M_DIM * C_DIM], g_Kl [M_DIM * C_DIM];
__device__ __nv_bfloat16  g_Vh [M_DIM * C_DIM], g_Vl [M_DIM * C_DIM];
__device__ __nv_bfloat16  g_Ah [M_DIM * C_DIM], g_Al [M_DIM * C_DIM];
// weights as [N][K] bf16 hi/lo (B operand of mma .col = K-major [N,K] rows)
__device__ __nv_bfloat16  g_Wqh[C_DIM * C_DIM], g_Wql[C_DIM * C_DIM];
__device__ __nv_bfloat16  g_Wkh[C_DIM * C_DIM], g_Wkl[C_DIM * C_DIM];
__device__ __nv_bfloat16  g_Wvh[C_DIM * C_DIM], g_Wvl[C_DIM * C_DIM];
__device__ __nv_bfloat16  g_Woh[C_DIM * C_DIM], g_Wol[C_DIM * C_DIM];

__device__ __forceinline__ void split_bf16(float v, __nv_bfloat16& h, __nv_bfloat16& l) {
    __nv_bfloat16 hi = __float2bfloat16(v);
    h = hi;
    l = __float2bfloat16(v - __bfloat162float(hi));
}
__device__ __forceinline__ uint32_t pack2(__nv_bfloat16 lo, __nv_bfloat16 hi) {
    __nv_bfloat162 t(lo, hi);
    return reinterpret_cast<uint32_t&>(t);
}

// ---------------------------------------------------------------------------
// Weight prep: [H,C,DH] -> [n=h*64+d][c] bf16 hi/lo; Wo [j][c] is already [N][K].
// ---------------------------------------------------------------------------
__global__ void prep_weights(const float* __restrict__ Wq,
                             const float* __restrict__ Wk,
                             const float* __restrict__ Wv,
                             const float* __restrict__ Wo)
{
    int i = blockIdx.x * blockDim.x + threadIdx.x;   // i = n*1024 + c
    int n = i >> 10;
    int c = i & 1023;
    int h = n >> 6;
    int d = n & 63;
    int src = (h << 16) + (c << 6) + d;              // h*C*DH + c*DH + d
    split_bf16(Wq[src], g_Wqh[i], g_Wql[i]);
    split_bf16(Wk[src], g_Wkh[i], g_Wkl[i]);
    split_bf16(Wv[src], g_Wvh[i], g_Wvl[i]);
    split_bf16(Wo[i],   g_Woh[i], g_Wol[i]);
}

__global__ void split_x(const float* __restrict__ x)
{
    int i = blockIdx.x * blockDim.x + threadIdx.x;
    split_bf16(x[i], g_Xh[i], g_Xl[i]);
}

// ===========================================================================
// PTX wrappers (all plain sm_80+ — assemble under compute_103)
// ===========================================================================
__device__ __forceinline__ uint32_t smem_u32(const void* p) {
    uint32_t a;
    asm("{ .reg .u64 t; cvta.to.shared.u64 t, %1; cvt.u32.u64 %0, t; }"
        : "=r"(a) : "l"(p));
    return a;
}
__device__ __forceinline__ void ldsm4(uint32_t* r, uint32_t addr) {
    asm volatile("ldmatrix.sync.aligned.m8n8.x4.shared.b16 {%0,%1,%2,%3}, [%4];"
                 : "=r"(r[0]), "=r"(r[1]), "=r"(r[2]), "=r"(r[3]) : "r"(addr));
}
__device__ __forceinline__ void ldsm4t(uint32_t* r, uint32_t addr) {
    asm volatile("ldmatrix.sync.aligned.m8n8.x4.trans.shared.b16 {%0,%1,%2,%3}, [%4];"
                 : "=r"(r[0]), "=r"(r[1]), "=r"(r[2]), "=r"(r[3]) : "r"(addr));
}
__device__ __forceinline__ void mma16816(float* c, const uint32_t* a, const uint32_t* b) {
    asm volatile("mma.sync.aligned.m16n8k16.row.col.f32.bf16.bf16.f32 "
                 "{%0,%1,%2,%3}, {%4,%5,%6,%7}, {%8,%9}, {%0,%1,%2,%3};"
                 : "+f"(c[0]), "+f"(c[1]), "+f"(c[2]), "+f"(c[3])
                 : "r"(a[0]), "r"(a[1]), "r"(a[2]), "r"(a[3]),
                   "r"(b[0]), "r"(b[1]));
}
#define CP_ASYNC16(saddr, gptr) \
    asm volatile("cp.async.cg.shared.global [%0], [%1], 16;" \
                 :: "r"(saddr), "l"(gptr) : "memory")
#define CP_COMMIT()  asm volatile("cp.async.commit_group;" ::: "memory")
#define CP_WAIT0()   asm volatile("cp.async.wait_group 0;" ::: "memory")

// ===========================================================================
// bf16 hi/lo GEMM, 2-stage double-buffered, K-chunk 32, ONE sync per chunk:
//   wait0 -> sync -> issue ch+1 (buf^1) -> compute (buf)
// The single sync both publishes chunk ch and proves buf^1 reads finished.
// Block 128x128, 8 warps (4m x 2n), pitch 80B, 81920B dynamic smem, 2 CTA/SM.
// Output: fp32 (+bias) if outh==null, else bf16 hi/lo split pair.
// ===========================================================================
#define PITCH   80
#define TILE_B  (128 * PITCH)          // 10240 bytes per tile
#define GSTG    (4 * TILE_B)           // 40960 per stage
#define GSM_TOT (2 * GSTG)             // 81920 dynamic
#define OA_H    0
#define OA_L    (TILE_B)
#define OB_H    (2 * TILE_B)
#define OB_L    (3 * TILE_B)

__global__ __launch_bounds__(256, 2)
void gemm_mma(const __nv_bfloat16* __restrict__ Ahp, const __nv_bfloat16* __restrict__ Alp,
              const __nv_bfloat16* __restrict__ Bhp, const __nv_bfloat16* __restrict__ Blp,
              float* __restrict__ Cmat, const float* __restrict__ bias,
              __nv_bfloat16* __restrict__ outh, __nv_bfloat16* __restrict__ outl,
              int Nglob, int Kglob)
{
    extern __shared__ char smdyn[];
    const uint32_t sb = smem_u32(smdyn);

    const int tid  = threadIdx.x;
    const int lane = tid & 31;
    const int wid  = tid >> 5;
    const int wm   = wid & 3;
    const int wn   = wid >> 2;

    const int row0 = blockIdx.y * 128;
    const int col0 = blockIdx.x * 128;

    // gmem load mapping: thread covers 16B blocks u = tid, tid+256 of each tile
    const int r0g = tid >> 2;                 // row of block u0 (0..63)
    const int c0g = tid & 3;                  // 16B col of block u0 (0..3)
    const __nv_bfloat16* pAh0 = Ahp + (size_t)(row0 + r0g) * Kglob + c0g * 8;
    const __nv_bfloat16* pAl0 = Alp + (size_t)(row0 + r0g) * Kglob + c0g * 8;
    const __nv_bfloat16* pBh0 = Bhp + (size_t)(col0 + r0g) * Kglob + c0g * 8;
    const __nv_bfloat16* pBl0 = Blp + (size_t)(col0 + r0g) * Kglob + c0g * 8;
    const size_t rowStep = (size_t)64 * Kglob;
    const uint32_t s0 = (uint32_t)(r0g * PITCH + c0g * 16);
    const uint32_t s1 = s0 + 64 * PITCH;

    const int a_row = (lane & 7) + ((lane >> 3) & 1) * 8;
    const int a_kb  = (lane >> 4);
    const int b_row = (lane & 7) + ((lane >> 4) & 1) * 8;
    const int b_kb  = (lane >> 3) & 1;

    float acc[2][8][4];
#pragma unroll
    for (int mi = 0; mi < 2; mi++)
#pragma unroll
        for (int nf = 0; nf < 8; nf++)
#pragma unroll
            for (int e = 0; e < 4; e++) acc[mi][nf][e] = 0.f;

    const int NCH = Kglob >> 5;        // chunks of 32

    // prologue: chunk 0 -> stage 0
    {
        const uint32_t base = sb;
        CP_ASYNC16(base + OA_H + s0, pAh0);
        CP_ASYNC16(base + OA_H + s1, pAh0 + rowStep);
        CP_ASYNC16(base + OA_L + s0, pAl0);
        CP_ASYNC16(base + OA_L + s1, pAl0 + rowStep);
        CP_ASYNC16(base + OB_H + s0, pBh0);
        CP_ASYNC16(base + OB_H + s1, pBh0 + rowStep);
        CP_ASYNC16(base + OB_L + s0, pBl0);
        CP_ASYNC16(base + OB_L + s1, pBl0 + rowStep);
        CP_COMMIT();
    }

    for (int ch = 0; ch < NCH; ch++) {
        const int buf = ch & 1;
        CP_WAIT0();                    // chunk ch landed (only group in flight)
        __syncthreads();               // publish ch; all warps done reading buf^1

        if (ch + 1 < NCH) {            // stream chunk ch+1 into the other stage
            const int k1 = (ch + 1) << 5;
            const uint32_t nb = sb + (buf ^ 1) * GSTG;
            CP_ASYNC16(nb + OA_H + s0, pAh0 + k1);
            CP_ASYNC16(nb + OA_H + s1, pAh0 + rowStep + k1);
            CP_ASYNC16(nb + OA_L + s0, pAl0 + k1);
            CP_ASYNC16(nb + OA_L + s1, pAl0 + rowStep + k1);
            CP_ASYNC16(nb + OB_H + s0, pBh0 + k1);
            CP_ASYNC16(nb + OB_H + s1, pBh0 + rowStep + k1);
            CP_ASYNC16(nb + OB_L + s0, pBl0 + k1);
            CP_ASYNC16(nb + OB_L + s1, pBl0 + rowStep + k1);
            CP_COMMIT();
        }

        const uint32_t base = sb + buf * GSTG;
#pragma unroll
        for (int ks = 0; ks < 2; ks++) {
            uint32_t ah[2][4], al[2][4], bh[4][4], bl[4][4];
#pragma unroll
            for (int mi = 0; mi < 2; mi++) {
                uint32_t ar = base + (uint32_t)((wm * 32 + mi * 16 + a_row) * PITCH
                                                + (2 * ks + a_kb) * 16);
                ldsm4(ah[mi], ar + OA_H);
                ldsm4(al[mi], ar + OA_L);
            }
#pragma unroll
            for (int p = 0; p < 4; p++) {
                uint32_t br = base + (uint32_t)((wn * 64 + p * 16 + b_row) * PITCH
                                                + (2 * ks + b_kb) * 16);
                ldsm4(bh[p], br + OB_H);
                ldsm4(bl[p], br + OB_L);
            }
#pragma unroll
            for (int mi = 0; mi < 2; mi++)
#pragma unroll
                for (int p = 0; p < 4; p++) {
                    mma16816(acc[mi][2 * p + 0], ah[mi], &bh[p][0]);
                    mma16816(acc[mi][2 * p + 0], ah[mi], &bl[p][0]);
                    mma16816(acc[mi][2 * p + 0], al[mi], &bh[p][0]);
                    mma16816(acc[mi][2 * p + 1], ah[mi], &bh[p][2]);
                    mma16816(acc[mi][2 * p + 1], ah[mi], &bl[p][2]);
                    mma16816(acc[mi][2 * p + 1], al[mi], &bh[p][2]);
                }
        }
    }

    const int tq = lane >> 2;
    const int tr = lane & 3;
#pragma unroll
    for (int mi = 0; mi < 2; mi++) {
        int rbase = row0 + wm * 32 + mi * 16 + tq;
#pragma unroll
        for (int nf = 0; nf < 8; nf++) {
            int col = col0 + wn * 64 + nf * 8 + tr * 2;
            if (outh) {
                __nv_bfloat16 h0, l0, h1, l1;
                split_bf16(acc[mi][nf][0], h0, l0);
                split_bf16(acc[mi][nf][1], h1, l1);
                *(uint32_t*)&outh[(size_t)rbase * Nglob + col] = pack2(h0, h1);
                *(uint32_t*)&outl[(size_t)rbase * Nglob + col] = pack2(l0, l1);
                split_bf16(acc[mi][nf][2], h0, l0);
                split_bf16(acc[mi][nf][3], h1, l1);
                *(uint32_t*)&outh[(size_t)(rbase + 8) * Nglob + col] = pack2(h0, h1);
                *(uint32_t*)&outl[(size_t)(rbase + 8) * Nglob + col] = pack2(l0, l1);
            } else {
                float bx = 0.f, by = 0.f;
                if (bias) { bx = bias[col]; by = bias[col + 1]; }
                float2 v0 = { acc[mi][nf][0] + bx, acc[mi][nf][1] + by };
                float2 v1 = { acc[mi][nf][2] + bx, acc[mi][nf][3] + by };
                *(float2*)&Cmat[(size_t)rbase * Nglob + col]       = v0;
                *(float2*)&Cmat[(size_t)(rbase + 8) * Nglob + col] = v1;
            }
        }
    }
}

// ===========================================================================
// Tensor-core causal flash attention, bf16 hi/lo compensated.
// NEW: double-buffered K/V stages (2 x 36864B dynamic), ONE sync per k-tile:
//   wait0 -> sync -> issue kt+1 (buf^1) -> S/softmax/PV on buf.
// Tile kt+1 streams during the whole compute of tile kt.
// ===========================================================================
#define AP 144
#define KV_T   (64 * AP)               // 9216 per array
#define KVSTG  (4 * KV_T)              // 36864 per stage (Kh|Kl|Vh|Vl)
#define ASM_TOT (2 * KVSTG)            // 73728 dynamic

__global__ __launch_bounds__(256, 1)
void attn_mma(const __nv_bfloat16* __restrict__ Qh, const __nv_bfloat16* __restrict__ Ql,
              const __nv_bfloat16* __restrict__ Kh, const __nv_bfloat16* __restrict__ Kl,
              const __nv_bfloat16* __restrict__ Vh, const __nv_bfloat16* __restrict__ Vl,
              __nv_bfloat16* __restrict__ Ao_h, __nv_bfloat16* __restrict__ Ao_l)
{
    extern __shared__ char smdyn[];
    const uint32_t sb = smem_u32(smdyn);

    const int tid  = threadIdx.x;
    const int lane = tid & 31;
    const int w    = tid >> 5;
    const int qt   = (int)gridDim.x - 1 - (int)blockIdx.x;   // big tiles first
    const int h    = blockIdx.y;
    const int b    = blockIdx.z;

    const int tq = lane >> 2;
    const int tr = lane & 3;
    const int a_row = (lane & 7) + ((lane >> 3) & 1) * 8;
    const int a_kb  = (lane >> 4);
    const int b_row = (lane & 7) + ((lane >> 4) & 1) * 8;
    const int b_kb  = (lane >> 3) & 1;

    // ---- stage Q hi/lo through buffer 0 region, preload frags to registers
    {
        const size_t qg0 = (size_t)(b * T_DIM + qt * 128) * C_DIM + h * DH_DIM;
#pragma unroll
        for (int k = 0; k < 4; k++) {
            int u = tid + k * 256;
            int r = u >> 3, c = u & 7;
            size_t ga = qg0 + (size_t)r * C_DIM + c * 8;
            uint32_t sa = (uint32_t)(r * AP + c * 16);
            CP_ASYNC16(sb + sa,             Qh + ga);   // Qh: rows 0..127
            CP_ASYNC16(sb + 2 * KV_T + sa,  Ql + ga);   // Ql at +18432
        }
        CP_COMMIT();
        CP_WAIT0();
        __syncthreads();
    }
    uint32_t qfh[4][4], qfl[4][4];
#pragma unroll
    for (int ks = 0; ks < 4; ks++) {
        uint32_t ar = sb + (uint32_t)((w * 16 + a_row) * AP + ks * 32 + a_kb * 16);
        ldsm4(qfh[ks], ar);
        ldsm4(qfl[ks], ar + 2 * KV_T);
    }
    __syncthreads();   // Q frags extracted; buffer 0 free for K/V

    float oacc[8][4];
#pragma unroll
    for (int nf = 0; nf < 8; nf++)
#pragma unroll
        for (int e = 0; e < 4; e++) oacc[nf][e] = 0.f;
    float m0 = -1e30f, m1 = -1e30f, l0 = 0.f, l1 = 0.f;

    const float SC = 0.18033688f;      // DH^-0.5 * log2(e)
    const size_t kvbase = (size_t)(b * T_DIM) * C_DIM + h * DH_DIM;
    const int ntiles = 2 * qt + 2;

    // prologue: tile 0 -> buffer 0 (K+V, one group)
    {
#pragma unroll
        for (int k = 0; k < 2; k++) {
            int u = tid + k * 256;
            int r = u >> 3, c = u & 7;
            size_t ga = kvbase + (size_t)r * C_DIM + c * 8;
            uint32_t sa = sb + (uint32_t)(r * AP + c * 16);
            CP_ASYNC16(sa + 0 * KV_T, Kh + ga);
            CP_ASYNC16(sa + 1 * KV_T, Kl + ga);
            CP_ASYNC16(sa + 2 * KV_T, Vh + ga);
            CP_ASYNC16(sa + 3 * KV_T, Vl + ga);
        }
        CP_COMMIT();
    }

    for (int kt = 0; kt < ntiles; kt++) {
        const uint32_t base = sb + (uint32_t)(kt & 1) * KVSTG;
        CP_WAIT0();                    // tile kt landed
        __syncthreads();               // publish kt; buf^1 reads finished

        if (kt + 1 < ntiles) {         // stream tile kt+1 into the other stage
            const uint32_t nb = sb + (uint32_t)((kt + 1) & 1) * KVSTG;
#pragma unroll
            for (int k = 0; k < 2; k++) {
                int u = tid + k * 256;
                int r = u >> 3, c = u & 7;
                size_t ga = kvbase + (size_t)((kt + 1) * 64 + r) * C_DIM + c * 8;
                uint32_t sa = nb + (uint32_t)(r * AP + c * 16);
                CP_ASYNC16(sa + 0 * KV_T, Kh + ga);
                CP_ASYNC16(sa + 1 * KV_T, Kl + ga);
                CP_ASYNC16(sa + 2 * KV_T, Vh + ga);
                CP_ASYNC16(sa + 3 * KV_T, Vl + ga);
            }
            CP_COMMIT();
        }

        // ---- S = Q K^T (3-term)
        float sacc[8][4];
#pragma unroll
        for (int nf = 0; nf < 8; nf++)
#pragma unroll
            for (int e = 0; e < 4; e++) sacc[nf][e] = 0.f;

#pragma unroll
        for (int ks = 0; ks < 4; ks++) {
            uint32_t kh4[4][4], kl4[4][4];
#pragma unroll
            for (int p = 0; p < 4; p++) {
                uint32_t br = base + (uint32_t)((p * 16 + b_row) * AP + ks * 32 + b_kb * 16);
                ldsm4(kh4[p], br);
                ldsm4(kl4[p], br + KV_T);
            }
#pragma unroll
            for (int p = 0; p < 4; p++) {
                mma16816(sacc[2 * p + 0], qfh[ks], &kh4[p][0]);
                mma16816(sacc[2 * p + 0], qfh[ks], &kl4[p][0]);
                mma16816(sacc[2 * p + 0], qfl[ks], &kh4[p][0]);
                mma16816(sacc[2 * p + 1], qfh[ks], &kh4[p][2]);
                mma16816(sacc[2 * p + 1], qfh[ks], &kl4[p][2]);
                mma16816(sacc[2 * p + 1], qfl[ks], &kh4[p][2]);
            }
        }

        // scale (base-2) + causal mask on diagonal tiles
        const bool need_mask = (kt >= 2 * qt);
#pragma unroll
        for (int nf = 0; nf < 8; nf++)
#pragma unroll
            for (int e = 0; e < 4; e++) {
                float s = sacc[nf][e] * SC;
                if (need_mask) {
                    int kg = kt * 64 + nf * 8 + 2 * tr + (e & 1);
                    int qg = qt * 128 + w * 16 + tq + ((e >> 1) << 3);
                    if (kg > qg) s = -1e30f;
                }
                sacc[nf][e] = s;
            }

        // row max (4-lane groups share a row)
        float mx0 = -1e30f, mx1 = -1e30f;
#pragma unroll
        for (int nf = 0; nf < 8; nf++) {
            mx0 = fmaxf(mx0, fmaxf(sacc[nf][0], sacc[nf][1]));
            mx1 = fmaxf(mx1, fmaxf(sacc[nf][2], sacc[nf][3]));
        }
        mx0 = fmaxf(mx0, __shfl_xor_sync(0xffffffffu, mx0, 1));
        mx0 = fmaxf(mx0, __shfl_xor_sync(0xffffffffu, mx0, 2));
        mx1 = fmaxf(mx1, __shfl_xor_sync(0xffffffffu, mx1, 1));
        mx1 = fmaxf(mx1, __shfl_xor_sync(0xffffffffu, mx1, 2));
        float mn0 = fmaxf(m0, mx0), mn1 = fmaxf(m1, mx1);
        float cr0 = exp2f(m0 - mn0), cr1 = exp2f(m1 - mn1);
        m0 = mn0; m1 = mn1;

        // exp + pack P as A-fragments (hi/lo)
        float rs0 = 0.f, rs1 = 0.f;
        uint32_t ph[4][4], pl[4][4];
#pragma unroll
        for (int kk = 0; kk < 4; kk++)
#pragma unroll
            for (int hh = 0; hh < 2; hh++) {
                int f = 2 * kk + hh;
                float e0 = exp2f(sacc[f][0] - mn0);
                float e1 = exp2f(sacc[f][1] - mn0);
                float e2 = exp2f(sacc[f][2] - mn1);
                float e3 = exp2f(sacc[f][3] - mn1);
                rs0 += e0 + e1;
                rs1 += e2 + e3;
                __nv_bfloat16 h0, q0, h1, q1, h2, q2, h3, q3;
                split_bf16(e0, h0, q0);
                split_bf16(e1, h1, q1);
                split_bf16(e2, h2, q2);
                split_bf16(e3, h3, q3);
                ph[kk][hh * 2 + 0] = pack2(h0, h1);
                ph[kk][hh * 2 + 1] = pack2(h2, h3);
                pl[kk][hh * 2 + 0] = pack2(q0, q1);
                pl[kk][hh * 2 + 1] = pack2(q2, q3);
            }
        rs0 += __shfl_xor_sync(0xffffffffu, rs0, 1);
        rs0 += __shfl_xor_sync(0xffffffffu, rs0, 2);
        rs1 += __shfl_xor_sync(0xffffffffu, rs1, 1);
        rs1 += __shfl_xor_sync(0xffffffffu, rs1, 2);
        l0 = l0 * cr0 + rs0;
        l1 = l1 * cr1 + rs1;
#pragma unroll
        for (int nf = 0; nf < 8; nf++) {
            oacc[nf][0] *= cr0;
            oacc[nf][1] *= cr0;
            oacc[nf][2] *= cr1;
            oacc[nf][3] *= cr1;
        }

        // ---- O += P V (3-term), V loaded transposed (already resident)
#pragma unroll
        for (int kk = 0; kk < 4; kk++)
#pragma unroll
            for (int p = 0; p < 4; p++) {
                uint32_t va = base + 2 * KV_T
                    + (uint32_t)((kk * 16 + (lane & 7) + ((lane >> 3) & 1) * 8) * AP
                                 + (p * 16 + (lane >> 4) * 8) * 2);
                uint32_t vh4[4], vl4[4];
                ldsm4t(vh4, va);
                ldsm4t(vl4, va + KV_T);
                mma16816(oacc[2 * p + 0], ph[kk], &vh4[0]);
                mma16816(oacc[2 * p + 0], ph[kk], &vl4[0]);
                mma16816(oacc[2 * p + 0], pl[kk], &vh4[0]);
                mma16816(oacc[2 * p + 1], ph[kk], &vh4[2]);
                mma16816(oacc[2 * p + 1], ph[kk], &vl4[2]);
                mma16816(oacc[2 * p + 1], pl[kk], &vh4[2]);
            }
    }

    // epilogue: normalize, split hi/lo, write [B,T, h*64+d]
    const float inv0 = 1.f / l0;
    const float inv1 = 1.f / l1;
    const size_t r0 = (size_t)(b * T_DIM + qt * 128 + w * 16 + tq);
    const size_t r1 = r0 + 8;
#pragma unroll
    for (int nf = 0; nf < 8; nf++) {
        int col = h * DH_DIM + nf * 8 + 2 * tr;
        __nv_bfloat16 h0, q0, h1, q1;
        split_bf16(oacc[nf][0] * inv0, h0, q0);
        split_bf16(oacc[nf][1] * inv0, h1, q1);
        *(uint32_t*)&Ao_h[r0 * C_DIM + col] = pack2(h0, h1);
        *(uint32_t*)&Ao_l[r0 * C_DIM + col] = pack2(q0, q1);
        split_bf16(oacc[nf][2] * inv1, h0, q0);
        split_bf16(oacc[nf][3] * inv1, h1, q1);
        *(uint32_t*)&Ao_h[r1 * C_DIM + col] = pack2(h0, h1);
        *(uint32_t*)&Ao_l[r1 * C_DIM + col] = pack2(q0, q1);
    }
}

// ===========================================================================
// Launch
// ===========================================================================
extern "C" void kernel_launch(void* const* d_in, const int* in_sizes, int n_in,
                              void* d_out, int out_size)
{
    (void)in_sizes; (void)n_in; (void)out_size;
    const float* x  = (const float*)d_in[0];
    const float* Wq = (const float*)d_in[1];
    const float* Wk = (const float*)d_in[2];
    const float* Wv = (const float*)d_in[3];
    const float* Wo = (const float*)d_in[4];
    const float* bo = (const float*)d_in[5];
    float* out = (float*)d_out;

    __nv_bfloat16 *pXh, *pXl, *pAh, *pAl;
    __nv_bfloat16 *pQh, *pQl, *pKh, *pKl, *pVh, *pVl;
    __nv_bfloat16 *pWqh, *pWql, *pWkh, *pWkl, *pWvh, *pWvl, *pWoh, *pWol;
    cudaGetSymbolAddress((void**)&pXh,  g_Xh);
    cudaGetSymbolAddress((void**)&pXl,  g_Xl);
    cudaGetSymbolAddress((void**)&pAh,  g_Ah);
    cudaGetSymbolAddress((void**)&pAl,  g_Al);
    cudaGetSymbolAddress((void**)&pQh,  g_Qh);
    cudaGetSymbolAddress((void**)&pQl,  g_Ql);
    cudaGetSymbolAddress((void**)&pKh,  g_Kh);
    cudaGetSymbolAddress((void**)&pKl,  g_Kl);
    cudaGetSymbolAddress((void**)&pVh,  g_Vh);
    cudaGetSymbolAddress((void**)&pVl,  g_Vl);
    cudaGetSymbolAddress((void**)&pWqh, g_Wqh);
    cudaGetSymbolAddress((void**)&pWql, g_Wql);
    cudaGetSymbolAddress((void**)&pWkh, g_Wkh);
    cudaGetSymbolAddress((void**)&pWkl, g_Wkl);
    cudaGetSymbolAddress((void**)&pWvh, g_Wvh);
    cudaGetSymbolAddress((void**)&pWvl, g_Wvl);
    cudaGetSymbolAddress((void**)&pWoh, g_Woh);
    cudaGetSymbolAddress((void**)&pWol, g_Wol);

    cudaFuncSetAttribute(gemm_mma, cudaFuncAttributeMaxDynamicSharedMemorySize, GSM_TOT);
    cudaFuncSetAttribute(attn_mma, cudaFuncAttributeMaxDynamicSharedMemorySize, ASM_TOT);

    // 1. splits / weight prep
    prep_weights<<<(C_DIM * C_DIM) / 256, 256>>>(Wq, Wk, Wv, Wo);
    split_x<<<(M_DIM * C_DIM) / 256, 256>>>(x);

    // 2. QKV projections -> bf16 hi/lo directly
    dim3 gg(C_DIM / 128, M_DIM / 128);   // (8, 64)
    gemm_mma<<<gg, 256, GSM_TOT>>>(pXh, pXl, pWqh, pWql, nullptr, nullptr, pQh, pQl, C_DIM, C_DIM);
    gemm_mma<<<gg, 256, GSM_TOT>>>(pXh, pXl, pWkh, pWkl, nullptr, nullptr, pKh, pKl, C_DIM, C_DIM);
    gemm_mma<<<gg, 256, GSM_TOT>>>(pXh, pXl, pWvh, pWvl, nullptr, nullptr, pVh, pVl, C_DIM, C_DIM);

    // 3. tensor-core causal flash attention -> bf16 hi/lo
    attn_mma<<<dim3(T_DIM / 128, H_DIM, B_DIM), 256, ASM_TOT>>>(pQh, pQl, pKh, pKl, pVh, pVl, pAh, pAl);

    // 4. output projection (fp32 out + bias)
    gemm_mma<<<gg, 256, GSM_TOT>>>(pAh, pAl, pWoh, pWol, out, bo, nullptr, nullptr, C_DIM, C_DIM);
}

// round 12
// speedup vs baseline: 1.1712x; 1.0017x over previous
#include <cuda_runtime.h>
#include <cuda_bf16.h>
#include <cstdint>

// Problem constants
#define C_DIM 1024
#define B_DIM 4
#define T_DIM 2048
#define H_DIM 16
#define DH_DIM 64
#define M_DIM (B_DIM * T_DIM)   // 8192

// ===========================================================================
// Scratch (__device__ globals; no cudaMalloc allowed)
// ===========================================================================
__device__ __nv_bfloat16  g_Xh [M_DIM * C_DIM];   // x hi/lo split
__device__ __nv_bfloat16  g_Xl [M_DIM * C_DIM];
__device__ __nv_bfloat16  g_Qh [M_DIM * C_DIM], g_Ql [M_DIM * C_DIM];
__device__ __nv_bfloat16  g_Kh [M_DIM * C_DIM], g_Kl [M_DIM * C_DIM];
__device__ __nv_bfloat16  g_Vh [M_DIM * C_DIM], g_Vl [M_DIM * C_DIM];
__device__ __nv_bfloat16  g_Ah [M_DIM * C_DIM], g_Al [M_DIM * C_DIM];
// weights as [N][K] bf16 hi/lo (B operand of mma .col = K-major [N,K] rows)
__device__ __nv_bfloat16  g_Wqh[C_DIM * C_DIM], g_Wql[C_DIM * C_DIM];
__device__ __nv_bfloat16  g_Wkh[C_DIM * C_DIM], g_Wkl[C_DIM * C_DIM];
__device__ __nv_bfloat16  g_Wvh[C_DIM * C_DIM], g_Wvl[C_DIM * C_DIM];
__device__ __nv_bfloat16  g_Woh[C_DIM * C_DIM], g_Wol[C_DIM * C_DIM];

__device__ __forceinline__ void split_bf16(float v, __nv_bfloat16& h, __nv_bfloat16& l) {
    __nv_bfloat16 hi = __float2bfloat16(v);
    h = hi;
    l = __float2bfloat16(v - __bfloat162float(hi));
}
__device__ __forceinline__ uint32_t pack2(__nv_bfloat16 lo, __nv_bfloat16 hi) {
    __nv_bfloat162 t(lo, hi);
    return reinterpret_cast<uint32_t&>(t);
}

// ---------------------------------------------------------------------------
// Weight prep: [H,C,DH] -> [n=h*64+d][c] bf16 hi/lo; Wo [j][c] is already [N][K].
// ---------------------------------------------------------------------------
__global__ void prep_weights(const float* __restrict__ Wq,
                             const float* __restrict__ Wk,
                             const float* __restrict__ Wv,
                             const float* __restrict__ Wo)
{
    int i = blockIdx.x * blockDim.x + threadIdx.x;   // i = n*1024 + c
    int n = i >> 10;
    int c = i & 1023;
    int h = n >> 6;
    int d = n & 63;
    int src = (h << 16) + (c << 6) + d;              // h*C*DH + c*DH + d
    split_bf16(Wq[src], g_Wqh[i], g_Wql[i]);
    split_bf16(Wk[src], g_Wkh[i], g_Wkl[i]);
    split_bf16(Wv[src], g_Wvh[i], g_Wvl[i]);
    split_bf16(Wo[i],   g_Woh[i], g_Wol[i]);
}

__global__ void split_x(const float* __restrict__ x)
{
    int i = blockIdx.x * blockDim.x + threadIdx.x;
    split_bf16(x[i], g_Xh[i], g_Xl[i]);
}

// ===========================================================================
// PTX wrappers (all plain sm_80+ — assemble under compute_103)
// ===========================================================================
__device__ __forceinline__ uint32_t smem_u32(const void* p) {
    uint32_t a;
    asm("{ .reg .u64 t; cvta.to.shared.u64 t, %1; cvt.u32.u64 %0, t; }"
        : "=r"(a) : "l"(p));
    return a;
}
__device__ __forceinline__ void ldsm4(uint32_t* r, uint32_t addr) {
    asm volatile("ldmatrix.sync.aligned.m8n8.x4.shared.b16 {%0,%1,%2,%3}, [%4];"
                 : "=r"(r[0]), "=r"(r[1]), "=r"(r[2]), "=r"(r[3]) : "r"(addr));
}
__device__ __forceinline__ void ldsm4t(uint32_t* r, uint32_t addr) {
    asm volatile("ldmatrix.sync.aligned.m8n8.x4.trans.shared.b16 {%0,%1,%2,%3}, [%4];"
                 : "=r"(r[0]), "=r"(r[1]), "=r"(r[2]), "=r"(r[3]) : "r"(addr));
}
__device__ __forceinline__ void mma16816(float* c, const uint32_t* a, const uint32_t* b) {
    asm volatile("mma.sync.aligned.m16n8k16.row.col.f32.bf16.bf16.f32 "
                 "{%0,%1,%2,%3}, {%4,%5,%6,%7}, {%8,%9}, {%0,%1,%2,%3};"
                 : "+f"(c[0]), "+f"(c[1]), "+f"(c[2]), "+f"(c[3])
                 : "r"(a[0]), "r"(a[1]), "r"(a[2]), "r"(a[3]),
                   "r"(b[0]), "r"(b[1]));
}
#define CP_ASYNC16(saddr, gptr) \
    asm volatile("cp.async.cg.shared.global [%0], [%1], 16;" \
                 :: "r"(saddr), "l"(gptr) : "memory")
#define CP_COMMIT()  asm volatile("cp.async.commit_group;" ::: "memory")
#define CP_WAIT0()   asm volatile("cp.async.wait_group 0;" ::: "memory")

// ===========================================================================
// bf16 hi/lo GEMM, 2-stage double-buffered, K-chunk 32, one sync per chunk.
// TERM-MAJOR MMA ORDER: per k16 step, issue all 16 AhBh MMAs (independent
// accumulators), then 16 AhBl, then 16 AlBh — dependent reuse distance 16.
// Per-accumulator order unchanged (HH,HL,LH) -> bit-identical results.
// ===========================================================================
#define PITCH   80
#define TILE_B  (128 * PITCH)          // 10240 bytes per tile
#define GSTG    (4 * TILE_B)           // 40960 per stage
#define GSM_TOT (2 * GSTG)             // 81920 dynamic
#define OA_H    0
#define OA_L    (TILE_B)
#define OB_H    (2 * TILE_B)
#define OB_L    (3 * TILE_B)

__global__ __launch_bounds__(256, 2)
void gemm_mma(const __nv_bfloat16* __restrict__ Ahp, const __nv_bfloat16* __restrict__ Alp,
              const __nv_bfloat16* __restrict__ Bhp, const __nv_bfloat16* __restrict__ Blp,
              float* __restrict__ Cmat, const float* __restrict__ bias,
              __nv_bfloat16* __restrict__ outh, __nv_bfloat16* __restrict__ outl,
              int Nglob, int Kglob)
{
    extern __shared__ char smdyn[];
    const uint32_t sb = smem_u32(smdyn);

    const int tid  = threadIdx.x;
    const int lane = tid & 31;
    const int wid  = tid >> 5;
    const int wm   = wid & 3;
    const int wn   = wid >> 2;

    const int row0 = blockIdx.y * 128;
    const int col0 = blockIdx.x * 128;

    const int r0g = tid >> 2;
    const int c0g = tid & 3;
    const __nv_bfloat16* pAh0 = Ahp + (size_t)(row0 + r0g) * Kglob + c0g * 8;
    const __nv_bfloat16* pAl0 = Alp + (size_t)(row0 + r0g) * Kglob + c0g * 8;
    const __nv_bfloat16* pBh0 = Bhp + (size_t)(col0 + r0g) * Kglob + c0g * 8;
    const __nv_bfloat16* pBl0 = Blp + (size_t)(col0 + r0g) * Kglob + c0g * 8;
    const size_t rowStep = (size_t)64 * Kglob;
    const uint32_t s0 = (uint32_t)(r0g * PITCH + c0g * 16);
    const uint32_t s1 = s0 + 64 * PITCH;

    const int a_row = (lane & 7) + ((lane >> 3) & 1) * 8;
    const int a_kb  = (lane >> 4);
    const int b_row = (lane & 7) + ((lane >> 4) & 1) * 8;
    const int b_kb  = (lane >> 3) & 1;

    float acc[2][8][4];
#pragma unroll
    for (int mi = 0; mi < 2; mi++)
#pragma unroll
        for (int nf = 0; nf < 8; nf++)
#pragma unroll
            for (int e = 0; e < 4; e++) acc[mi][nf][e] = 0.f;

    const int NCH = Kglob >> 5;        // chunks of 32

    // prologue: chunk 0 -> stage 0
    {
        const uint32_t base = sb;
        CP_ASYNC16(base + OA_H + s0, pAh0);
        CP_ASYNC16(base + OA_H + s1, pAh0 + rowStep);
        CP_ASYNC16(base + OA_L + s0, pAl0);
        CP_ASYNC16(base + OA_L + s1, pAl0 + rowStep);
        CP_ASYNC16(base + OB_H + s0, pBh0);
        CP_ASYNC16(base + OB_H + s1, pBh0 + rowStep);
        CP_ASYNC16(base + OB_L + s0, pBl0);
        CP_ASYNC16(base + OB_L + s1, pBl0 + rowStep);
        CP_COMMIT();
    }

    for (int ch = 0; ch < NCH; ch++) {
        const int buf = ch & 1;
        CP_WAIT0();
        __syncthreads();               // publish ch; buf^1 reads finished

        if (ch + 1 < NCH) {
            const int k1 = (ch + 1) << 5;
            const uint32_t nb = sb + (buf ^ 1) * GSTG;
            CP_ASYNC16(nb + OA_H + s0, pAh0 + k1);
            CP_ASYNC16(nb + OA_H + s1, pAh0 + rowStep + k1);
            CP_ASYNC16(nb + OA_L + s0, pAl0 + k1);
            CP_ASYNC16(nb + OA_L + s1, pAl0 + rowStep + k1);
            CP_ASYNC16(nb + OB_H + s0, pBh0 + k1);
            CP_ASYNC16(nb + OB_H + s1, pBh0 + rowStep + k1);
            CP_ASYNC16(nb + OB_L + s0, pBl0 + k1);
            CP_ASYNC16(nb + OB_L + s1, pBl0 + rowStep + k1);
            CP_COMMIT();
        }

        const uint32_t base = sb + buf * GSTG;
#pragma unroll
        for (int ks = 0; ks < 2; ks++) {
            uint32_t ah[2][4], al[2][4], bh[4][4], bl[4][4];
#pragma unroll
            for (int mi = 0; mi < 2; mi++) {
                uint32_t ar = base + (uint32_t)((wm * 32 + mi * 16 + a_row) * PITCH
                                                + (2 * ks + a_kb) * 16);
                ldsm4(ah[mi], ar + OA_H);
                ldsm4(al[mi], ar + OA_L);
            }
#pragma unroll
            for (int p = 0; p < 4; p++) {
                uint32_t br = base + (uint32_t)((wn * 64 + p * 16 + b_row) * PITCH
                                                + (2 * ks + b_kb) * 16);
                ldsm4(bh[p], br + OB_H);
                ldsm4(bl[p], br + OB_L);
            }
            // term 1: Ah*Bh — 16 independent MMAs
#pragma unroll
            for (int mi = 0; mi < 2; mi++)
#pragma unroll
                for (int p = 0; p < 4; p++) {
                    mma16816(acc[mi][2 * p + 0], ah[mi], &bh[p][0]);
                    mma16816(acc[mi][2 * p + 1], ah[mi], &bh[p][2]);
                }
            // term 2: Ah*Bl
#pragma unroll
            for (int mi = 0; mi < 2; mi++)
#pragma unroll
                for (int p = 0; p < 4; p++) {
                    mma16816(acc[mi][2 * p + 0], ah[mi], &bl[p][0]);
                    mma16816(acc[mi][2 * p + 1], ah[mi], &bl[p][2]);
                }
            // term 3: Al*Bh
#pragma unroll
            for (int mi = 0; mi < 2; mi++)
#pragma unroll
                for (int p = 0; p < 4; p++) {
                    mma16816(acc[mi][2 * p + 0], al[mi], &bh[p][0]);
                    mma16816(acc[mi][2 * p + 1], al[mi], &bh[p][2]);
                }
        }
    }

    const int tq = lane >> 2;
    const int tr = lane & 3;
#pragma unroll
    for (int mi = 0; mi < 2; mi++) {
        int rbase = row0 + wm * 32 + mi * 16 + tq;
#pragma unroll
        for (int nf = 0; nf < 8; nf++) {
            int col = col0 + wn * 64 + nf * 8 + tr * 2;
            if (outh) {
                __nv_bfloat16 h0, l0, h1, l1;
                split_bf16(acc[mi][nf][0], h0, l0);
                split_bf16(acc[mi][nf][1], h1, l1);
                *(uint32_t*)&outh[(size_t)rbase * Nglob + col] = pack2(h0, h1);
                *(uint32_t*)&outl[(size_t)rbase * Nglob + col] = pack2(l0, l1);
                split_bf16(acc[mi][nf][2], h0, l0);
                split_bf16(acc[mi][nf][3], h1, l1);
                *(uint32_t*)&outh[(size_t)(rbase + 8) * Nglob + col] = pack2(h0, h1);
                *(uint32_t*)&outl[(size_t)(rbase + 8) * Nglob + col] = pack2(l0, l1);
            } else {
                float bx = 0.f, by = 0.f;
                if (bias) { bx = bias[col]; by = bias[col + 1]; }
                float2 v0 = { acc[mi][nf][0] + bx, acc[mi][nf][1] + by };
                float2 v1 = { acc[mi][nf][2] + bx, acc[mi][nf][3] + by };
                *(float2*)&Cmat[(size_t)rbase * Nglob + col]       = v0;
                *(float2*)&Cmat[(size_t)(rbase + 8) * Nglob + col] = v1;
            }
        }
    }
}

// ===========================================================================
// Tensor-core causal flash attention, bf16 hi/lo, double-buffered K/V,
// one sync per tile. TERM-MAJOR MMA ORDER in S and PV phases (8 independent
// MMAs per term); V fragments for all pairs hoisted before PV MMAs.
// ===========================================================================
#define AP 144
#define KV_T   (64 * AP)               // 9216 per array
#define KVSTG  (4 * KV_T)              // 36864 per stage (Kh|Kl|Vh|Vl)
#define ASM_TOT (2 * KVSTG)            // 73728 dynamic

__global__ __launch_bounds__(256, 1)
void attn_mma(const __nv_bfloat16* __restrict__ Qh, const __nv_bfloat16* __restrict__ Ql,
              const __nv_bfloat16* __restrict__ Kh, const __nv_bfloat16* __restrict__ Kl,
              const __nv_bfloat16* __restrict__ Vh, const __nv_bfloat16* __restrict__ Vl,
              __nv_bfloat16* __restrict__ Ao_h, __nv_bfloat16* __restrict__ Ao_l)
{
    extern __shared__ char smdyn[];
    const uint32_t sb = smem_u32(smdyn);

    const int tid  = threadIdx.x;
    const int lane = tid & 31;
    const int w    = tid >> 5;
    const int qt   = (int)gridDim.x - 1 - (int)blockIdx.x;   // big tiles first
    const int h    = blockIdx.y;
    const int b    = blockIdx.z;

    const int tq = lane >> 2;
    const int tr = lane & 3;
    const int a_row = (lane & 7) + ((lane >> 3) & 1) * 8;
    const int a_kb  = (lane >> 4);
    const int b_row = (lane & 7) + ((lane >> 4) & 1) * 8;
    const int b_kb  = (lane >> 3) & 1;

    // ---- stage Q hi/lo through buffer 0 region, preload frags to registers
    {
        const size_t qg0 = (size_t)(b * T_DIM + qt * 128) * C_DIM + h * DH_DIM;
#pragma unroll
        for (int k = 0; k < 4; k++) {
            int u = tid + k * 256;
            int r = u >> 3, c = u & 7;
            size_t ga = qg0 + (size_t)r * C_DIM + c * 8;
            uint32_t sa = (uint32_t)(r * AP + c * 16);
            CP_ASYNC16(sb + sa,             Qh + ga);
            CP_ASYNC16(sb + 2 * KV_T + sa,  Ql + ga);
        }
        CP_COMMIT();
        CP_WAIT0();
        __syncthreads();
    }
    uint32_t qfh[4][4], qfl[4][4];
#pragma unroll
    for (int ks = 0; ks < 4; ks++) {
        uint32_t ar = sb + (uint32_t)((w * 16 + a_row) * AP + ks * 32 + a_kb * 16);
        ldsm4(qfh[ks], ar);
        ldsm4(qfl[ks], ar + 2 * KV_T);
    }
    __syncthreads();   // Q frags extracted; buffer 0 free for K/V

    float oacc[8][4];
#pragma unroll
    for (int nf = 0; nf < 8; nf++)
#pragma unroll
        for (int e = 0; e < 4; e++) oacc[nf][e] = 0.f;
    float m0 = -1e30f, m1 = -1e30f, l0 = 0.f, l1 = 0.f;

    const float SC = 0.18033688f;      // DH^-0.5 * log2(e)
    const size_t kvbase = (size_t)(b * T_DIM) * C_DIM + h * DH_DIM;
    const int ntiles = 2 * qt + 2;

    // prologue: tile 0 -> buffer 0
    {
#pragma unroll
        for (int k = 0; k < 2; k++) {
            int u = tid + k * 256;
            int r = u >> 3, c = u & 7;
            size_t ga = kvbase + (size_t)r * C_DIM + c * 8;
            uint32_t sa = sb + (uint32_t)(r * AP + c * 16);
            CP_ASYNC16(sa + 0 * KV_T, Kh + ga);
            CP_ASYNC16(sa + 1 * KV_T, Kl + ga);
            CP_ASYNC16(sa + 2 * KV_T, Vh + ga);
            CP_ASYNC16(sa + 3 * KV_T, Vl + ga);
        }
        CP_COMMIT();
    }

    for (int kt = 0; kt < ntiles; kt++) {
        const uint32_t base = sb + (uint32_t)(kt & 1) * KVSTG;
        CP_WAIT0();
        __syncthreads();               // publish kt; buf^1 reads finished

        if (kt + 1 < ntiles) {
            const uint32_t nb = sb + (uint32_t)((kt + 1) & 1) * KVSTG;
#pragma unroll
            for (int k = 0; k < 2; k++) {
                int u = tid + k * 256;
                int r = u >> 3, c = u & 7;
                size_t ga = kvbase + (size_t)((kt + 1) * 64 + r) * C_DIM + c * 8;
                uint32_t sa = nb + (uint32_t)(r * AP + c * 16);
                CP_ASYNC16(sa + 0 * KV_T, Kh + ga);
                CP_ASYNC16(sa + 1 * KV_T, Kl + ga);
                CP_ASYNC16(sa + 2 * KV_T, Vh + ga);
                CP_ASYNC16(sa + 3 * KV_T, Vl + ga);
            }
            CP_COMMIT();
        }

        // ---- S = Q K^T (3-term, term-major)
        float sacc[8][4];
#pragma unroll
        for (int nf = 0; nf < 8; nf++)
#pragma unroll
            for (int e = 0; e < 4; e++) sacc[nf][e] = 0.f;

#pragma unroll
        for (int ks = 0; ks < 4; ks++) {
            uint32_t kh4[4][4], kl4[4][4];
#pragma unroll
            for (int p = 0; p < 4; p++) {
                uint32_t br = base + (uint32_t)((p * 16 + b_row) * AP + ks * 32 + b_kb * 16);
                ldsm4(kh4[p], br);
                ldsm4(kl4[p], br + KV_T);
            }
            // term 1: Qh*Kh — 8 independent MMAs
#pragma unroll
            for (int p = 0; p < 4; p++) {
                mma16816(sacc[2 * p + 0], qfh[ks], &kh4[p][0]);
                mma16816(sacc[2 * p + 1], qfh[ks], &kh4[p][2]);
            }
            // term 2: Qh*Kl
#pragma unroll
            for (int p = 0; p < 4; p++) {
                mma16816(sacc[2 * p + 0], qfh[ks], &kl4[p][0]);
                mma16816(sacc[2 * p + 1], qfh[ks], &kl4[p][2]);
            }
            // term 3: Ql*Kh
#pragma unroll
            for (int p = 0; p < 4; p++) {
                mma16816(sacc[2 * p + 0], qfl[ks], &kh4[p][0]);
                mma16816(sacc[2 * p + 1], qfl[ks], &kh4[p][2]);
            }
        }

        // scale (base-2) + causal mask on diagonal tiles
        const bool need_mask = (kt >= 2 * qt);
#pragma unroll
        for (int nf = 0; nf < 8; nf++)
#pragma unroll
            for (int e = 0; e < 4; e++) {
                float s = sacc[nf][e] * SC;
                if (need_mask) {
                    int kg = kt * 64 + nf * 8 + 2 * tr + (e & 1);
                    int qg = qt * 128 + w * 16 + tq + ((e >> 1) << 3);
                    if (kg > qg) s = -1e30f;
                }
                sacc[nf][e] = s;
            }

        // row max (4-lane groups share a row)
        float mx0 = -1e30f, mx1 = -1e30f;
#pragma unroll
        for (int nf = 0; nf < 8; nf++) {
            mx0 = fmaxf(mx0, fmaxf(sacc[nf][0], sacc[nf][1]));
            mx1 = fmaxf(mx1, fmaxf(sacc[nf][2], sacc[nf][3]));
        }
        mx0 = fmaxf(mx0, __shfl_xor_sync(0xffffffffu, mx0, 1));
        mx0 = fmaxf(mx0, __shfl_xor_sync(0xffffffffu, mx0, 2));
        mx1 = fmaxf(mx1, __shfl_xor_sync(0xffffffffu, mx1, 1));
        mx1 = fmaxf(mx1, __shfl_xor_sync(0xffffffffu, mx1, 2));
        float mn0 = fmaxf(m0, mx0), mn1 = fmaxf(m1, mx1);
        float cr0 = exp2f(m0 - mn0), cr1 = exp2f(m1 - mn1);
        m0 = mn0; m1 = mn1;

        // exp + pack P as A-fragments (hi/lo)
        float rs0 = 0.f, rs1 = 0.f;
        uint32_t ph[4][4], pl[4][4];
#pragma unroll
        for (int kk = 0; kk < 4; kk++)
#pragma unroll
            for (int hh = 0; hh < 2; hh++) {
                int f = 2 * kk + hh;
                float e0 = exp2f(sacc[f][0] - mn0);
                float e1 = exp2f(sacc[f][1] - mn0);
                float e2 = exp2f(sacc[f][2] - mn1);
                float e3 = exp2f(sacc[f][3] - mn1);
                rs0 += e0 + e1;
                rs1 += e2 + e3;
                __nv_bfloat16 h0, q0, h1, q1, h2, q2, h3, q3;
                split_bf16(e0, h0, q0);
                split_bf16(e1, h1, q1);
                split_bf16(e2, h2, q2);
                split_bf16(e3, h3, q3);
                ph[kk][hh * 2 + 0] = pack2(h0, h1);
                ph[kk][hh * 2 + 1] = pack2(h2, h3);
                pl[kk][hh * 2 + 0] = pack2(q0, q1);
                pl[kk][hh * 2 + 1] = pack2(q2, q3);
            }
        rs0 += __shfl_xor_sync(0xffffffffu, rs0, 1);
        rs0 += __shfl_xor_sync(0xffffffffu, rs0, 2);
        rs1 += __shfl_xor_sync(0xffffffffu, rs1, 1);
        rs1 += __shfl_xor_sync(0xffffffffu, rs1, 2);
        l0 = l0 * cr0 + rs0;
        l1 = l1 * cr1 + rs1;
#pragma unroll
        for (int nf = 0; nf < 8; nf++) {
            oacc[nf][0] *= cr0;
            oacc[nf][1] *= cr0;
            oacc[nf][2] *= cr1;
            oacc[nf][3] *= cr1;
        }

        // ---- O += P V (3-term, term-major; V frags hoisted per kk)
#pragma unroll
        for (int kk = 0; kk < 4; kk++) {
            uint32_t vh4[4][4], vl4[4][4];
#pragma unroll
            for (int p = 0; p < 4; p++) {
                uint32_t va = base + 2 * KV_T
                    + (uint32_t)((kk * 16 + (lane & 7) + ((lane >> 3) & 1) * 8) * AP
                                 + (p * 16 + (lane >> 4) * 8) * 2);
                ldsm4t(vh4[p], va);
                ldsm4t(vl4[p], va + KV_T);
            }
            // term 1: Ph*Vh — 8 independent MMAs
#pragma unroll
            for (int p = 0; p < 4; p++) {
                mma16816(oacc[2 * p + 0], ph[kk], &vh4[p][0]);
                mma16816(oacc[2 * p + 1], ph[kk], &vh4[p][2]);
            }
            // term 2: Ph*Vl
#pragma unroll
            for (int p = 0; p < 4; p++) {
                mma16816(oacc[2 * p + 0], ph[kk], &vl4[p][0]);
                mma16816(oacc[2 * p + 1], ph[kk], &vl4[p][2]);
            }
            // term 3: Pl*Vh
#pragma unroll
            for (int p = 0; p < 4; p++) {
                mma16816(oacc[2 * p + 0], pl[kk], &vh4[p][0]);
                mma16816(oacc[2 * p + 1], pl[kk], &vh4[p][2]);
            }
        }
    }

    // epilogue: normalize, split hi/lo, write [B,T, h*64+d]
    const float inv0 = 1.f / l0;
    const float inv1 = 1.f / l1;
    const size_t r0 = (size_t)(b * T_DIM + qt * 128 + w * 16 + tq);
    const size_t r1 = r0 + 8;
#pragma unroll
    for (int nf = 0; nf < 8; nf++) {
        int col = h * DH_DIM + nf * 8 + 2 * tr;
        __nv_bfloat16 h0, q0, h1, q1;
        split_bf16(oacc[nf][0] * inv0, h0, q0);
        split_bf16(oacc[nf][1] * inv0, h1, q1);
        *(uint32_t*)&Ao_h[r0 * C_DIM + col] = pack2(h0, h1);
        *(uint32_t*)&Ao_l[r0 * C_DIM + col] = pack2(q0, q1);
        split_bf16(oacc[nf][2] * inv1, h0, q0);
        split_bf16(oacc[nf][3] * inv1, h1, q1);
        *(uint32_t*)&Ao_h[r1 * C_DIM + col] = pack2(h0, h1);
        *(uint32_t*)&Ao_l[r1 * C_DIM + col] = pack2(q0, q1);
    }
}

// ===========================================================================
// Launch
// ===========================================================================
extern "C" void kernel_launch(void* const* d_in, const int* in_sizes, int n_in,
                              void* d_out, int out_size)
{
    (void)in_sizes; (void)n_in; (void)out_size;
    const float* x  = (const float*)d_in[0];
    const float* Wq = (const float*)d_in[1];
    const float* Wk = (const float*)d_in[2];
    const float* Wv = (const float*)d_in[3];
    const float* Wo = (const float*)d_in[4];
    const float* bo = (const float*)d_in[5];
    float* out = (float*)d_out;

    __nv_bfloat16 *pXh, *pXl, *pAh, *pAl;
    __nv_bfloat16 *pQh, *pQl, *pKh, *pKl, *pVh, *pVl;
    __nv_bfloat16 *pWqh, *pWql, *pWkh, *pWkl, *pWvh, *pWvl, *pWoh, *pWol;
    cudaGetSymbolAddress((void**)&pXh,  g_Xh);
    cudaGetSymbolAddress((void**)&pXl,  g_Xl);
    cudaGetSymbolAddress((void**)&pAh,  g_Ah);
    cudaGetSymbolAddress((void**)&pAl,  g_Al);
    cudaGetSymbolAddress((void**)&pQh,  g_Qh);
    cudaGetSymbolAddress((void**)&pQl,  g_Ql);
    cudaGetSymbolAddress((void**)&pKh,  g_Kh);
    cudaGetSymbolAddress((void**)&pKl,  g_Kl);
    cudaGetSymbolAddress((void**)&pVh,  g_Vh);
    cudaGetSymbolAddress((void**)&pVl,  g_Vl);
    cudaGetSymbolAddress((void**)&pWqh, g_Wqh);
    cudaGetSymbolAddress((void**)&pWql, g_Wql);
    cudaGetSymbolAddress((void**)&pWkh, g_Wkh);
    cudaGetSymbolAddress((void**)&pWkl, g_Wkl);
    cudaGetSymbolAddress((void**)&pWvh, g_Wvh);
    cudaGetSymbolAddress((void**)&pWvl, g_Wvl);
    cudaGetSymbolAddress((void**)&pWoh, g_Woh);
    cudaGetSymbolAddress((void**)&pWol, g_Wol);

    cudaFuncSetAttribute(gemm_mma, cudaFuncAttributeMaxDynamicSharedMemorySize, GSM_TOT);
    cudaFuncSetAttribute(attn_mma, cudaFuncAttributeMaxDynamicSharedMemorySize, ASM_TOT);

    // 1. splits / weight prep
    prep_weights<<<(C_DIM * C_DIM) / 256, 256>>>(Wq, Wk, Wv, Wo);
    split_x<<<(M_DIM * C_DIM) / 256, 256>>>(x);

    // 2. QKV projections -> bf16 hi/lo directly
    dim3 gg(C_DIM / 128, M_DIM / 128);   // (8, 64)
    gemm_mma<<<gg, 256, GSM_TOT>>>(pXh, pXl, pWqh, pWql, nullptr, nullptr, pQh, pQl, C_DIM, C_DIM);
    gemm_mma<<<gg, 256, GSM_TOT>>>(pXh, pXl, pWkh, pWkl, nullptr, nullptr, pKh, pKl, C_DIM, C_DIM);
    gemm_mma<<<gg, 256, GSM_TOT>>>(pXh, pXl, pWvh, pWvl, nullptr, nullptr, pVh, pVl, C_DIM, C_DIM);

    // 3. tensor-core causal flash attention -> bf16 hi/lo
    attn_mma<<<dim3(T_DIM / 128, H_DIM, B_DIM), 256, ASM_TOT>>>(pQh, pQl, pKh, pKl, pVh, pVl, pAh, pAl);

    // 4. output projection (fp32 out + bias)
    gemm_mma<<<gg, 256, GSM_TOT>>>(pAh, pAl, pWoh, pWol, out, bo, nullptr, nullptr, C_DIM, C_DIM);
}

// round 16
// speedup vs baseline: 1.4288x; 1.2200x over previous
#include <cuda_runtime.h>
#include <cuda_fp16.h>
#include <cstdint>

// Problem constants
#define C_DIM 1024
#define B_DIM 4
#define T_DIM 2048
#define H_DIM 16
#define DH_DIM 64
#define M_DIM (B_DIM * T_DIM)   // 8192

// ===========================================================================
// Scratch (__device__ globals; no cudaMalloc allowed)
// ===========================================================================
__device__ __half  g_X  [M_DIM * C_DIM];               // x as fp16 (hi only)
__device__ __half  g_Qh [M_DIM * C_DIM], g_Ql [M_DIM * C_DIM];
__device__ __half  g_Kh [M_DIM * C_DIM], g_Kl [M_DIM * C_DIM];
__device__ __half  g_Vh [M_DIM * C_DIM], g_Vl [M_DIM * C_DIM];
__device__ __half  g_A  [M_DIM * C_DIM];               // attention out (hi only)
// weights as [N][K] fp16 hi/lo (B operand of mma .col = K-major [N,K] rows)
__device__ __half  g_Wqh[C_DIM * C_DIM], g_Wql[C_DIM * C_DIM];
__device__ __half  g_Wkh[C_DIM * C_DIM], g_Wkl[C_DIM * C_DIM];
__device__ __half  g_Wvh[C_DIM * C_DIM], g_Wvl[C_DIM * C_DIM];
__device__ __half  g_Woh[C_DIM * C_DIM], g_Wol[C_DIM * C_DIM];

__device__ __forceinline__ void split_f16(float v, __half& h, __half& l) {
    __half hi = __float2half_rn(v);
    h = hi;
    l = __float2half_rn(v - __half2float(hi));
}
__device__ __forceinline__ uint32_t pack2h(__half lo, __half hi) {
    __half2 t = __halves2half2(lo, hi);
    return reinterpret_cast<uint32_t&>(t);
}

// ---------------------------------------------------------------------------
// Weight prep: [H,C,DH] -> [n=h*64+d][c] fp16 hi/lo; Wo [j][c] is already [N][K].
// ---------------------------------------------------------------------------
__global__ void prep_weights(const float* __restrict__ Wq,
                             const float* __restrict__ Wk,
                             const float* __restrict__ Wv,
                             const float* __restrict__ Wo)
{
    int i = blockIdx.x * blockDim.x + threadIdx.x;   // i = n*1024 + c
    int n = i >> 10;
    int c = i & 1023;
    int h = n >> 6;
    int d = n & 63;
    int src = (h << 16) + (c << 6) + d;              // h*C*DH + c*DH + d
    split_f16(Wq[src], g_Wqh[i], g_Wql[i]);
    split_f16(Wk[src], g_Wkh[i], g_Wkl[i]);
    split_f16(Wv[src], g_Wvh[i], g_Wvl[i]);
    split_f16(Wo[i],   g_Woh[i], g_Wol[i]);
}

__global__ void split_x(const float* __restrict__ x)
{
    int i = blockIdx.x * blockDim.x + threadIdx.x;
    g_X[i] = __float2half_rn(x[i]);
}

// ===========================================================================
// PTX wrappers (all plain sm_80+ — assemble under compute_103)
// ===========================================================================
__device__ __forceinline__ uint32_t smem_u32(const void* p) {
    uint32_t a;
    asm("{ .reg .u64 t; cvta.to.shared.u64 t, %1; cvt.u32.u64 %0, t; }"
        : "=r"(a) : "l"(p));
    return a;
}
__device__ __forceinline__ void ldsm4(uint32_t* r, uint32_t addr) {
    asm volatile("ldmatrix.sync.aligned.m8n8.x4.shared.b16 {%0,%1,%2,%3}, [%4];"
                 : "=r"(r[0]), "=r"(r[1]), "=r"(r[2]), "=r"(r[3]) : "r"(addr));
}
__device__ __forceinline__ void ldsm4t(uint32_t* r, uint32_t addr) {
    asm volatile("ldmatrix.sync.aligned.m8n8.x4.trans.shared.b16 {%0,%1,%2,%3}, [%4];"
                 : "=r"(r[0]), "=r"(r[1]), "=r"(r[2]), "=r"(r[3]) : "r"(addr));
}
__device__ __forceinline__ void mma16816(float* c, const uint32_t* a, const uint32_t* b) {
    asm volatile("mma.sync.aligned.m16n8k16.row.col.f32.f16.f16.f32 "
                 "{%0,%1,%2,%3}, {%4,%5,%6,%7}, {%8,%9}, {%0,%1,%2,%3};"
                 : "+f"(c[0]), "+f"(c[1]), "+f"(c[2]), "+f"(c[3])
                 : "r"(a[0]), "r"(a[1]), "r"(a[2]), "r"(a[3]),
                   "r"(b[0]), "r"(b[1]));
}
#define CP_ASYNC16(saddr, gptr) \
    asm volatile("cp.async.cg.shared.global [%0], [%1], 16;" \
                 :: "r"(saddr), "l"(gptr) : "memory")
#define CP_COMMIT()  asm volatile("cp.async.commit_group;" ::: "memory")
#define CP_WAIT0()   asm volatile("cp.async.wait_group 0;" ::: "memory")

// ===========================================================================
// fp16 GEMM, 2-term weight compensation: C = Ah*Bh + Ah*Bl (A fp16, B ~fp25).
// 2-stage double-buffered, K-chunk 32, one sync per chunk, term-major order.
// Block 128x128, 8 warps (4m x 2n), pitch 80B; stage = 3 tiles x 10240B =
// 30720B; 2 stages = 61440B dynamic. 2 CTAs/SM.
// Output: fp32 (+bias) if outh==null, else fp16 hi/lo split pair.
// ===========================================================================
#define PITCH   80
#define TILE_B  (128 * PITCH)          // 10240 bytes per tile
#define GSTG    (3 * TILE_B)           // 30720 per stage (A | Bh | Bl)
#define GSM_TOT (2 * GSTG)             // 61440 dynamic
#define OA      0
#define OB_H    (TILE_B)
#define OB_L    (2 * TILE_B)

__global__ __launch_bounds__(256, 2)
void gemm_mma(const __half* __restrict__ Ap,
              const __half* __restrict__ Bhp, const __half* __restrict__ Blp,
              float* __restrict__ Cmat, const float* __restrict__ bias,
              __half* __restrict__ outh, __half* __restrict__ outl,
              int Nglob, int Kglob)
{
    extern __shared__ char smdyn[];
    const uint32_t sb = smem_u32(smdyn);

    const int tid  = threadIdx.x;
    const int lane = tid & 31;
    const int wid  = tid >> 5;
    const int wm   = wid & 3;
    const int wn   = wid >> 2;

    const int row0 = blockIdx.y * 128;
    const int col0 = blockIdx.x * 128;

    const int r0g = tid >> 2;
    const int c0g = tid & 3;
    const __half* pA0  = Ap  + (size_t)(row0 + r0g) * Kglob + c0g * 8;
    const __half* pBh0 = Bhp + (size_t)(col0 + r0g) * Kglob + c0g * 8;
    const __half* pBl0 = Blp + (size_t)(col0 + r0g) * Kglob + c0g * 8;
    const size_t rowStep = (size_t)64 * Kglob;
    const uint32_t s0 = (uint32_t)(r0g * PITCH + c0g * 16);
    const uint32_t s1 = s0 + 64 * PITCH;

    const int a_row = (lane & 7) + ((lane >> 3) & 1) * 8;
    const int a_kb  = (lane >> 4);
    const int b_row = (lane & 7) + ((lane >> 4) & 1) * 8;
    const int b_kb  = (lane >> 3) & 1;

    float acc[2][8][4];
#pragma unroll
    for (int mi = 0; mi < 2; mi++)
#pragma unroll
        for (int nf = 0; nf < 8; nf++)
#pragma unroll
            for (int e = 0; e < 4; e++) acc[mi][nf][e] = 0.f;

    const int NCH = Kglob >> 5;        // chunks of 32

    // prologue: chunk 0 -> stage 0
    {
        const uint32_t base = sb;
        CP_ASYNC16(base + OA   + s0, pA0);
        CP_ASYNC16(base + OA   + s1, pA0 + rowStep);
        CP_ASYNC16(base + OB_H + s0, pBh0);
        CP_ASYNC16(base + OB_H + s1, pBh0 + rowStep);
        CP_ASYNC16(base + OB_L + s0, pBl0);
        CP_ASYNC16(base + OB_L + s1, pBl0 + rowStep);
        CP_COMMIT();
    }

    for (int ch = 0; ch < NCH; ch++) {
        const int buf = ch & 1;
        CP_WAIT0();
        __syncthreads();               // publish ch; buf^1 reads finished

        if (ch + 1 < NCH) {
            const int k1 = (ch + 1) << 5;
            const uint32_t nb = sb + (buf ^ 1) * GSTG;
            CP_ASYNC16(nb + OA   + s0, pA0 + k1);
            CP_ASYNC16(nb + OA   + s1, pA0 + rowStep + k1);
            CP_ASYNC16(nb + OB_H + s0, pBh0 + k1);
            CP_ASYNC16(nb + OB_H + s1, pBh0 + rowStep + k1);
            CP_ASYNC16(nb + OB_L + s0, pBl0 + k1);
            CP_ASYNC16(nb + OB_L + s1, pBl0 + rowStep + k1);
            CP_COMMIT();
        }

        const uint32_t base = sb + buf * GSTG;
#pragma unroll
        for (int ks = 0; ks < 2; ks++) {
            uint32_t ah[2][4], bh[4][4], bl[4][4];
#pragma unroll
            for (int mi = 0; mi < 2; mi++) {
                uint32_t ar = base + (uint32_t)((wm * 32 + mi * 16 + a_row) * PITCH
                                                + (2 * ks + a_kb) * 16);
                ldsm4(ah[mi], ar + OA);
            }
#pragma unroll
            for (int p = 0; p < 4; p++) {
                uint32_t br = base + (uint32_t)((wn * 64 + p * 16 + b_row) * PITCH
                                                + (2 * ks + b_kb) * 16);
                ldsm4(bh[p], br + OB_H);
                ldsm4(bl[p], br + OB_L);
            }
            // term 1: Ah*Bh — 16 independent MMAs
#pragma unroll
            for (int mi = 0; mi < 2; mi++)
#pragma unroll
                for (int p = 0; p < 4; p++) {
                    mma16816(acc[mi][2 * p + 0], ah[mi], &bh[p][0]);
                    mma16816(acc[mi][2 * p + 1], ah[mi], &bh[p][2]);
                }
            // term 2: Ah*Bl
#pragma unroll
            for (int mi = 0; mi < 2; mi++)
#pragma unroll
                for (int p = 0; p < 4; p++) {
                    mma16816(acc[mi][2 * p + 0], ah[mi], &bl[p][0]);
                    mma16816(acc[mi][2 * p + 1], ah[mi], &bl[p][2]);
                }
        }
    }

    const int tq = lane >> 2;
    const int tr = lane & 3;
#pragma unroll
    for (int mi = 0; mi < 2; mi++) {
        int rbase = row0 + wm * 32 + mi * 16 + tq;
#pragma unroll
        for (int nf = 0; nf < 8; nf++) {
            int col = col0 + wn * 64 + nf * 8 + tr * 2;
            if (outh) {
                __half h0, l0, h1, l1;
                split_f16(acc[mi][nf][0], h0, l0);
                split_f16(acc[mi][nf][1], h1, l1);
                *(uint32_t*)&outh[(size_t)rbase * Nglob + col] = pack2h(h0, h1);
                *(uint32_t*)&outl[(size_t)rbase * Nglob + col] = pack2h(l0, l1);
                split_f16(acc[mi][nf][2], h0, l0);
                split_f16(acc[mi][nf][3], h1, l1);
                *(uint32_t*)&outh[(size_t)(rbase + 8) * Nglob + col] = pack2h(h0, h1);
                *(uint32_t*)&outl[(size_t)(rbase + 8) * Nglob + col] = pack2h(l0, l1);
            } else {
                float bx = 0.f, by = 0.f;
                if (bias) { bx = bias[col]; by = bias[col + 1]; }
                float2 v0 = { acc[mi][nf][0] + bx, acc[mi][nf][1] + by };
                float2 v1 = { acc[mi][nf][2] + bx, acc[mi][nf][3] + by };
                *(float2*)&Cmat[(size_t)rbase * Nglob + col]       = v0;
                *(float2*)&Cmat[(size_t)(rbase + 8) * Nglob + col] = v1;
            }
        }
    }
}

// ===========================================================================
// Tensor-core causal flash attention, fp16 hi/lo, 3-term compensation
// (error class 2^-22 — negligible). Double-buffered K/V, one sync per tile,
// term-major MMA order. Output: fp16 hi only (Wo GEMM uses single A stream).
// ===========================================================================
#define AP 144
#define KV_T   (64 * AP)               // 9216 per array
#define KVSTG  (4 * KV_T)              // 36864 per stage (Kh|Kl|Vh|Vl)
#define ASM_TOT (2 * KVSTG)            // 73728 dynamic

__global__ __launch_bounds__(256, 1)
void attn_mma(const __half* __restrict__ Qh, const __half* __restrict__ Ql,
              const __half* __restrict__ Kh, const __half* __restrict__ Kl,
              const __half* __restrict__ Vh, const __half* __restrict__ Vl,
              __half* __restrict__ Ao)
{
    extern __shared__ char smdyn[];
    const uint32_t sb = smem_u32(smdyn);

    const int tid  = threadIdx.x;
    const int lane = tid & 31;
    const int w    = tid >> 5;
    const int qt   = (int)gridDim.x - 1 - (int)blockIdx.x;   // big tiles first
    const int h    = blockIdx.y;
    const int b    = blockIdx.z;

    const int tq = lane >> 2;
    const int tr = lane & 3;
    const int a_row = (lane & 7) + ((lane >> 3) & 1) * 8;
    const int a_kb  = (lane >> 4);
    const int b_row = (lane & 7) + ((lane >> 4) & 1) * 8;
    const int b_kb  = (lane >> 3) & 1;

    // ---- stage Q hi/lo through buffer 0 region, preload frags to registers
    {
        const size_t qg0 = (size_t)(b * T_DIM + qt * 128) * C_DIM + h * DH_DIM;
#pragma unroll
        for (int k = 0; k < 4; k++) {
            int u = tid + k * 256;
            int r = u >> 3, c = u & 7;
            size_t ga = qg0 + (size_t)r * C_DIM + c * 8;
            uint32_t sa = (uint32_t)(r * AP + c * 16);
            CP_ASYNC16(sb + sa,             Qh + ga);
            CP_ASYNC16(sb + 2 * KV_T + sa,  Ql + ga);
        }
        CP_COMMIT();
        CP_WAIT0();
        __syncthreads();
    }
    uint32_t qfh[4][4], qfl[4][4];
#pragma unroll
    for (int ks = 0; ks < 4; ks++) {
        uint32_t ar = sb + (uint32_t)((w * 16 + a_row) * AP + ks * 32 + a_kb * 16);
        ldsm4(qfh[ks], ar);
        ldsm4(qfl[ks], ar + 2 * KV_T);
    }
    __syncthreads();   // Q frags extracted; buffer 0 free for K/V

    float oacc[8][4];
#pragma unroll
    for (int nf = 0; nf < 8; nf++)
#pragma unroll
        for (int e = 0; e < 4; e++) oacc[nf][e] = 0.f;
    float m0 = -1e30f, m1 = -1e30f, l0 = 0.f, l1 = 0.f;

    const float SC = 0.18033688f;      // DH^-0.5 * log2(e)
    const size_t kvbase = (size_t)(b * T_DIM) * C_DIM + h * DH_DIM;
    const int ntiles = 2 * qt + 2;

    // prologue: tile 0 -> buffer 0
    {
#pragma unroll
        for (int k = 0; k < 2; k++) {
            int u = tid + k * 256;
            int r = u >> 3, c = u & 7;
            size_t ga = kvbase + (size_t)r * C_DIM + c * 8;
            uint32_t sa = sb + (uint32_t)(r * AP + c * 16);
            CP_ASYNC16(sa + 0 * KV_T, Kh + ga);
            CP_ASYNC16(sa + 1 * KV_T, Kl + ga);
            CP_ASYNC16(sa + 2 * KV_T, Vh + ga);
            CP_ASYNC16(sa + 3 * KV_T, Vl + ga);
        }
        CP_COMMIT();
    }

    for (int kt = 0; kt < ntiles; kt++) {
        const uint32_t base = sb + (uint32_t)(kt & 1) * KVSTG;
        CP_WAIT0();
        __syncthreads();               // publish kt; buf^1 reads finished

        if (kt + 1 < ntiles) {
            const uint32_t nb = sb + (uint32_t)((kt + 1) & 1) * KVSTG;
#pragma unroll
            for (int k = 0; k < 2; k++) {
                int u = tid + k * 256;
                int r = u >> 3, c = u & 7;
                size_t ga = kvbase + (size_t)((kt + 1) * 64 + r) * C_DIM + c * 8;
                uint32_t sa = nb + (uint32_t)(r * AP + c * 16);
                CP_ASYNC16(sa + 0 * KV_T, Kh + ga);
                CP_ASYNC16(sa + 1 * KV_T, Kl + ga);
                CP_ASYNC16(sa + 2 * KV_T, Vh + ga);
                CP_ASYNC16(sa + 3 * KV_T, Vl + ga);
            }
            CP_COMMIT();
        }

        // ---- S = Q K^T (3-term, term-major)
        float sacc[8][4];
#pragma unroll
        for (int nf = 0; nf < 8; nf++)
#pragma unroll
            for (int e = 0; e < 4; e++) sacc[nf][e] = 0.f;

#pragma unroll
        for (int ks = 0; ks < 4; ks++) {
            uint32_t kh4[4][4], kl4[4][4];
#pragma unroll
            for (int p = 0; p < 4; p++) {
                uint32_t br = base + (uint32_t)((p * 16 + b_row) * AP + ks * 32 + b_kb * 16);
                ldsm4(kh4[p], br);
                ldsm4(kl4[p], br + KV_T);
            }
#pragma unroll
            for (int p = 0; p < 4; p++) {
                mma16816(sacc[2 * p + 0], qfh[ks], &kh4[p][0]);
                mma16816(sacc[2 * p + 1], qfh[ks], &kh4[p][2]);
            }
#pragma unroll
            for (int p = 0; p < 4; p++) {
                mma16816(sacc[2 * p + 0], qfh[ks], &kl4[p][0]);
                mma16816(sacc[2 * p + 1], qfh[ks], &kl4[p][2]);
            }
#pragma unroll
            for (int p = 0; p < 4; p++) {
                mma16816(sacc[2 * p + 0], qfl[ks], &kh4[p][0]);
                mma16816(sacc[2 * p + 1], qfl[ks], &kh4[p][2]);
            }
        }

        // scale (base-2) + causal mask on diagonal tiles
        const bool need_mask = (kt >= 2 * qt);
#pragma unroll
        for (int nf = 0; nf < 8; nf++)
#pragma unroll
            for (int e = 0; e < 4; e++) {
                float s = sacc[nf][e] * SC;
                if (need_mask) {
                    int kg = kt * 64 + nf * 8 + 2 * tr + (e & 1);
                    int qg = qt * 128 + w * 16 + tq + ((e >> 1) << 3);
                    if (kg > qg) s = -1e30f;
                }
                sacc[nf][e] = s;
            }

        // row max (4-lane groups share a row)
        float mx0 = -1e30f, mx1 = -1e30f;
#pragma unroll
        for (int nf = 0; nf < 8; nf++) {
            mx0 = fmaxf(mx0, fmaxf(sacc[nf][0], sacc[nf][1]));
            mx1 = fmaxf(mx1, fmaxf(sacc[nf][2], sacc[nf][3]));
        }
        mx0 = fmaxf(mx0, __shfl_xor_sync(0xffffffffu, mx0, 1));
        mx0 = fmaxf(mx0, __shfl_xor_sync(0xffffffffu, mx0, 2));
        mx1 = fmaxf(mx1, __shfl_xor_sync(0xffffffffu, mx1, 1));
        mx1 = fmaxf(mx1, __shfl_xor_sync(0xffffffffu, mx1, 2));
        float mn0 = fmaxf(m0, mx0), mn1 = fmaxf(m1, mx1);
        float cr0 = exp2f(m0 - mn0), cr1 = exp2f(m1 - mn1);
        m0 = mn0; m1 = mn1;

        // exp + pack P as A-fragments (hi/lo fp16)
        float rs0 = 0.f, rs1 = 0.f;
        uint32_t ph[4][4], pl[4][4];
#pragma unroll
        for (int kk = 0; kk < 4; kk++)
#pragma unroll
            for (int hh = 0; hh < 2; hh++) {
                int f = 2 * kk + hh;
                float e0 = exp2f(sacc[f][0] - mn0);
                float e1 = exp2f(sacc[f][1] - mn0);
                float e2 = exp2f(sacc[f][2] - mn1);
                float e3 = exp2f(sacc[f][3] - mn1);
                rs0 += e0 + e1;
                rs1 += e2 + e3;
                __half h0, q0, h1, q1, h2, q2, h3, q3;
                split_f16(e0, h0, q0);
                split_f16(e1, h1, q1);
                split_f16(e2, h2, q2);
                split_f16(e3, h3, q3);
                ph[kk][hh * 2 + 0] = pack2h(h0, h1);
                ph[kk][hh * 2 + 1] = pack2h(h2, h3);
                pl[kk][hh * 2 + 0] = pack2h(q0, q1);
                pl[kk][hh * 2 + 1] = pack2h(q2, q3);
            }
        rs0 += __shfl_xor_sync(0xffffffffu, rs0, 1);
        rs0 += __shfl_xor_sync(0xffffffffu, rs0, 2);
        rs1 += __shfl_xor_sync(0xffffffffu, rs1, 1);
        rs1 += __shfl_xor_sync(0xffffffffu, rs1, 2);
        l0 = l0 * cr0 + rs0;
        l1 = l1 * cr1 + rs1;
#pragma unroll
        for (int nf = 0; nf < 8; nf++) {
            oacc[nf][0] *= cr0;
            oacc[nf][1] *= cr0;
            oacc[nf][2] *= cr1;
            oacc[nf][3] *= cr1;
        }

        // ---- O += P V (3-term, term-major; V frags hoisted per kk)
#pragma unroll
        for (int kk = 0; kk < 4; kk++) {
            uint32_t vh4[4][4], vl4[4][4];
#pragma unroll
            for (int p = 0; p < 4; p++) {
                uint32_t va = base + 2 * KV_T
                    + (uint32_t)((kk * 16 + (lane & 7) + ((lane >> 3) & 1) * 8) * AP
                                 + (p * 16 + (lane >> 4) * 8) * 2);
                ldsm4t(vh4[p], va);
                ldsm4t(vl4[p], va + KV_T);
            }
#pragma unroll
            for (int p = 0; p < 4; p++) {
                mma16816(oacc[2 * p + 0], ph[kk], &vh4[p][0]);
                mma16816(oacc[2 * p + 1], ph[kk], &vh4[p][2]);
            }
#pragma unroll
            for (int p = 0; p < 4; p++) {
                mma16816(oacc[2 * p + 0], ph[kk], &vl4[p][0]);
                mma16816(oacc[2 * p + 1], ph[kk], &vl4[p][2]);
            }
#pragma unroll
            for (int p = 0; p < 4; p++) {
                mma16816(oacc[2 * p + 0], pl[kk], &vh4[p][0]);
                mma16816(oacc[2 * p + 1], pl[kk], &vh4[p][2]);
            }
        }
    }

    // epilogue: normalize, write fp16 hi only [B,T, h*64+d]
    const float inv0 = 1.f / l0;
    const float inv1 = 1.f / l1;
    const size_t r0 = (size_t)(b * T_DIM + qt * 128 + w * 16 + tq);
    const size_t r1 = r0 + 8;
#pragma unroll
    for (int nf = 0; nf < 8; nf++) {
        int col = h * DH_DIM + nf * 8 + 2 * tr;
        *(uint32_t*)&Ao[r0 * C_DIM + col] =
            pack2h(__float2half_rn(oacc[nf][0] * inv0), __float2half_rn(oacc[nf][1] * inv0));
        *(uint32_t*)&Ao[r1 * C_DIM + col] =
            pack2h(__float2half_rn(oacc[nf][2] * inv1), __float2half_rn(oacc[nf][3] * inv1));
    }
}

// ===========================================================================
// Launch
// ===========================================================================
extern "C" void kernel_launch(void* const* d_in, const int* in_sizes, int n_in,
                              void* d_out, int out_size)
{
    (void)in_sizes; (void)n_in; (void)out_size;
    const float* x  = (const float*)d_in[0];
    const float* Wq = (const float*)d_in[1];
    const float* Wk = (const float*)d_in[2];
    const float* Wv = (const float*)d_in[3];
    const float* Wo = (const float*)d_in[4];
    const float* bo = (const float*)d_in[5];
    float* out = (float*)d_out;

    __half *pX, *pA;
    __half *pQh, *pQl, *pKh, *pKl, *pVh, *pVl;
    __half *pWqh, *pWql, *pWkh, *pWkl, *pWvh, *pWvl, *pWoh, *pWol;
    cudaGetSymbolAddress((void**)&pX,   g_X);
    cudaGetSymbolAddress((void**)&pA,   g_A);
    cudaGetSymbolAddress((void**)&pQh,  g_Qh);
    cudaGetSymbolAddress((void**)&pQl,  g_Ql);
    cudaGetSymbolAddress((void**)&pKh,  g_Kh);
    cudaGetSymbolAddress((void**)&pKl,  g_Kl);
    cudaGetSymbolAddress((void**)&pVh,  g_Vh);
    cudaGetSymbolAddress((void**)&pVl,  g_Vl);
    cudaGetSymbolAddress((void**)&pWqh, g_Wqh);
    cudaGetSymbolAddress((void**)&pWql, g_Wql);
    cudaGetSymbolAddress((void**)&pWkh, g_Wkh);
    cudaGetSymbolAddress((void**)&pWkl, g_Wkl);
    cudaGetSymbolAddress((void**)&pWvh, g_Wvh);
    cudaGetSymbolAddress((void**)&pWvl, g_Wvl);
    cudaGetSymbolAddress((void**)&pWoh, g_Woh);
    cudaGetSymbolAddress((void**)&pWol, g_Wol);

    cudaFuncSetAttribute(gemm_mma, cudaFuncAttributeMaxDynamicSharedMemorySize, GSM_TOT);
    cudaFuncSetAttribute(attn_mma, cudaFuncAttributeMaxDynamicSharedMemorySize, ASM_TOT);

    // 1. splits / weight prep
    prep_weights<<<(C_DIM * C_DIM) / 256, 256>>>(Wq, Wk, Wv, Wo);
    split_x<<<(M_DIM * C_DIM) / 256, 256>>>(x);

    // 2. QKV projections -> fp16 hi/lo
    dim3 gg(C_DIM / 128, M_DIM / 128);   // (8, 64)
    gemm_mma<<<gg, 256, GSM_TOT>>>(pX, pWqh, pWql, nullptr, nullptr, pQh, pQl, C_DIM, C_DIM);
    gemm_mma<<<gg, 256, GSM_TOT>>>(pX, pWkh, pWkl, nullptr, nullptr, pKh, pKl, C_DIM, C_DIM);
    gemm_mma<<<gg, 256, GSM_TOT>>>(pX, pWvh, pWvl, nullptr, nullptr, pVh, pVl, C_DIM, C_DIM);

    // 3. tensor-core causal flash attention -> fp16 (hi only)
    attn_mma<<<dim3(T_DIM / 128, H_DIM, B_DIM), 256, ASM_TOT>>>(pQh, pQl, pKh, pKl, pVh, pVl, pA);

    // 4. output projection (fp32 out + bias)
    gemm_mma<<<gg, 256, GSM_TOT>>>(pA, pWoh, pWol, out, bo, nullptr, nullptr, C_DIM, C_DIM);
}